// round 6
// baseline (speedup 1.0000x reference)
#include <cuda_runtime.h>

#define Bb 2
#define Nn 128
#define Cc 256
#define BN2 (Bb*Nn*Nn)        // 32768 edge rows
#define NODES_SZ (Bb*Nn*Cc)   // 65536
#define EDGES_SZ (BN2*Cc)     // 8388608
#define KN_ 101
#define KE_ 7
#define ALPHA 0.2f
#define LN_EPS 1e-5f
#define NEG_BIG (-1e30f)

// ---------------- scratch (device globals: allocation-free) ----------------
__device__ float g_eA[EDGES_SZ];
__device__ float g_eB[EDGES_SZ];
__device__ float g_n0[NODES_SZ];
__device__ float g_n1[NODES_SZ];
__device__ float g_ai[NODES_SZ];
__device__ float g_aj[NODES_SZ];
__device__ float g_nf[NODES_SZ];
__device__ float g_s[Bb*Nn];
__device__ float g_v[Cc];
__device__ float g_w[Cc];
__device__ float g_dotv[BN2];

// ---------------- tf32 helpers ---------------------------------------------
__device__ __forceinline__ unsigned f2tf(float f)
{
    unsigned r;
    asm("cvt.rna.tf32.f32 %0, %1;" : "=r"(r) : "f"(f));
    return r;
}
__device__ __forceinline__ uint4 f2tf4(float4 v)
{
    return make_uint4(f2tf(v.x), f2tf(v.y), f2tf(v.z), f2tf(v.w));
}
__device__ __forceinline__ void mma16n8k8(float& c0, float& c1, float& c2, float& c3,
                                          unsigned a0, unsigned a1, unsigned a2, unsigned a3,
                                          unsigned b0, unsigned b1)
{
    asm volatile("mma.sync.aligned.m16n8k8.row.col.f32.tf32.tf32.f32 "
                 "{%0,%1,%2,%3}, {%4,%5,%6,%7}, {%8,%9}, {%0,%1,%2,%3};"
                 : "+f"(c0), "+f"(c1), "+f"(c2), "+f"(c3)
                 : "r"(a0), "r"(a1), "r"(a2), "r"(a3), "r"(b0), "r"(b1));
}

// ---------------- small generic GEMM: out[m,n] = A[m,:]·W[n,:] + bias ------
__global__ void gemm_small(const float* __restrict__ A, const float* __restrict__ W,
                           const float* __restrict__ bias, float* __restrict__ out,
                           int M, int N, int K, int ldw)
{
    __shared__ float As[16][16];
    __shared__ float Ws[16][17];
    int tx = threadIdx.x, ty = threadIdx.y;
    int m = blockIdx.y * 16 + ty;
    int n = blockIdx.x * 16 + tx;
    float acc = 0.f;
    for (int k0 = 0; k0 < K; k0 += 16) {
        As[ty][tx] = (m < M) ? A[m * K + k0 + tx] : 0.f;
        int nn = blockIdx.x * 16 + ty;
        Ws[ty][tx] = (nn < N) ? W[(size_t)nn * ldw + k0 + tx] : 0.f;
        __syncthreads();
#pragma unroll
        for (int kk = 0; kk < 16; kk++) acc += As[ty][kk] * Ws[tx][kk];
        __syncthreads();
    }
    if (m < M && n < N) {
        float b = bias ? bias[n] : 0.f;
        out[m * N + n] = acc + b;
    }
}

// ---------------- edge GEMM, tf32, software-pipelined ----------------------
// 128x128 tile, 8 warps of 64x32, BK=32.
// MODE 0: out = A@W^T + bias[n]
// MODE 1: out = lrelu(A@W^T + ai[b,i,n] + aj[b,j,n]) * mask[m] + A[m,n]
#define ESTRIDE 36
template<int MODE>
__global__ void __launch_bounds__(256, 2)
edge_mma(const float* __restrict__ A, const float* __restrict__ W,
         int K, int ldw, const float* __restrict__ bias,
         const float* __restrict__ ai, const float* __restrict__ aj,
         const float* __restrict__ mask, float* __restrict__ out)
{
    __shared__ unsigned As[128 * ESTRIDE];
    __shared__ unsigned Bs[128 * ESTRIDE];
    int tid = threadIdx.x;
    int lane = tid & 31, wid = tid >> 5;
    int warp_m = (wid & 1) * 64;
    int warp_n = (wid >> 1) * 32;
    int mbase = blockIdx.y * 128;
    int nbase = blockIdx.x * 128;

    float c[4][4][4];
#pragma unroll
    for (int mi = 0; mi < 4; mi++)
#pragma unroll
        for (int ni = 0; ni < 4; ni++)
#pragma unroll
            for (int q = 0; q < 4; q++) c[mi][ni][q] = 0.f;

    int lrow = tid >> 1;
    int lk0 = (tid & 1) * 16;
    const float* Aptr = A + (size_t)(mbase + lrow) * K + lk0;
    const float* Wptr = W + (size_t)(nbase + lrow) * ldw + lk0;
    unsigned* asw = &As[lrow * ESTRIDE + lk0];
    unsigned* bsw = &Bs[lrow * ESTRIDE + lk0];
    int lg = lane >> 2, lt = lane & 3;

    // prologue: stage k-tile 0 in registers
    float4 ra[4], rb[4];
#pragma unroll
    for (int q = 0; q < 4; q++) {
        ra[q] = *(const float4*)(Aptr + 4 * q);
        rb[q] = *(const float4*)(Wptr + 4 * q);
    }

    for (int kt = 0; kt < K; kt += 32) {
        // drain staged regs to smem
#pragma unroll
        for (int q = 0; q < 4; q++) {
            *(uint4*)(asw + 4 * q) = f2tf4(ra[q]);
            *(uint4*)(bsw + 4 * q) = f2tf4(rb[q]);
        }
        __syncthreads();
        // issue next-stage loads; latency hidden behind the MMAs below
        if (kt + 32 < K) {
#pragma unroll
            for (int q = 0; q < 4; q++) {
                ra[q] = *(const float4*)(Aptr + kt + 32 + 4 * q);
                rb[q] = *(const float4*)(Wptr + kt + 32 + 4 * q);
            }
        }
#pragma unroll
        for (int k8 = 0; k8 < 4; k8++) {
            int kc = k8 * 8 + lt;
            unsigned af[4][4], bf[4][2];
#pragma unroll
            for (int mi = 0; mi < 4; mi++) {
                int r0 = warp_m + mi * 16 + lg;
                af[mi][0] = As[r0 * ESTRIDE + kc];
                af[mi][1] = As[(r0 + 8) * ESTRIDE + kc];
                af[mi][2] = As[r0 * ESTRIDE + kc + 4];
                af[mi][3] = As[(r0 + 8) * ESTRIDE + kc + 4];
            }
#pragma unroll
            for (int ni = 0; ni < 4; ni++) {
                int n0 = warp_n + ni * 8 + lg;
                bf[ni][0] = Bs[n0 * ESTRIDE + kc];
                bf[ni][1] = Bs[n0 * ESTRIDE + kc + 4];
            }
#pragma unroll
            for (int mi = 0; mi < 4; mi++)
#pragma unroll
                for (int ni = 0; ni < 4; ni++)
                    mma16n8k8(c[mi][ni][0], c[mi][ni][1], c[mi][ni][2], c[mi][ni][3],
                              af[mi][0], af[mi][1], af[mi][2], af[mi][3],
                              bf[ni][0], bf[ni][1]);
        }
        __syncthreads();
    }

    // epilogue
#pragma unroll
    for (int mi = 0; mi < 4; mi++) {
#pragma unroll
        for (int half = 0; half < 2; half++) {
            int m = mbase + warp_m + mi * 16 + lg + half * 8;
            int b = m >> 14;
            int i = (m >> 7) & 127;
            int j = m & 127;
            float mv = 0.f;
            const float* aip = nullptr;
            const float* ajp = nullptr;
            if (MODE == 1) {
                mv = mask[m];
                aip = &ai[(size_t)((b << 7) + i) * 256];
                ajp = &aj[(size_t)((b << 7) + j) * 256];
            }
#pragma unroll
            for (int ni = 0; ni < 4; ni++) {
                int col = nbase + warp_n + ni * 8 + 2 * lt;
                float v0 = c[mi][ni][2 * half + 0];
                float v1 = c[mi][ni][2 * half + 1];
                if (MODE == 0) {
                    float2 bv = *(const float2*)&bias[col];
                    v0 += bv.x; v1 += bv.y;
                } else {
                    float2 av2 = *(const float2*)&aip[col];
                    float2 aj2 = *(const float2*)&ajp[col];
                    float2 rs2 = *(const float2*)&A[(size_t)m * 256 + col];
                    v0 += av2.x + aj2.x;
                    v1 += av2.y + aj2.y;
                    v0 = (v0 > 0.f ? v0 : ALPHA * v0) * mv + rs2.x;
                    v1 = (v1 > 0.f ? v1 : ALPHA * v1) * mv + rs2.y;
                }
                *(float2*)&out[(size_t)m * 256 + col] = make_float2(v0, v1);
            }
        }
    }
}

// ---------------- node GEMMs: 64x64 tiles, 48 blocks, pipelined ------------
// z=0 -> ai (Wb1, ldw 768), z=1 -> aj (Wb3, ldw 768), z=2 -> nf (Wf, ldw 256)
__global__ void __launch_bounds__(128)
node3_mma(const float* __restrict__ A, const float* __restrict__ Wb_l,
          const float* __restrict__ Wf_l,
          float* __restrict__ ai, float* __restrict__ aj, float* __restrict__ nf)
{
    __shared__ unsigned As[64 * ESTRIDE];
    __shared__ unsigned Bs[64 * ESTRIDE];
    int z = blockIdx.z;
    const float* W = (z == 0) ? Wb_l : (z == 1) ? (Wb_l + 512) : Wf_l;
    int ldw = (z == 2) ? 256 : 768;
    float* out = (z == 0) ? ai : (z == 1) ? aj : nf;

    int tid = threadIdx.x;
    int lane = tid & 31, wid = tid >> 5;          // 4 warps
    int warp_m = (wid & 1) * 32;
    int warp_n = (wid >> 1) * 32;
    int mbase = blockIdx.y * 64;
    int nbase = blockIdx.x * 64;

    float c[2][4][4];
#pragma unroll
    for (int mi = 0; mi < 2; mi++)
#pragma unroll
        for (int ni = 0; ni < 4; ni++)
#pragma unroll
            for (int q = 0; q < 4; q++) c[mi][ni][q] = 0.f;

    int lrow = tid >> 1;               // 0..63
    int lk0 = (tid & 1) * 16;
    const float* Aptr = A + (size_t)(mbase + lrow) * 256 + lk0;
    const float* Wptr = W + (size_t)(nbase + lrow) * ldw + lk0;
    unsigned* asw = &As[lrow * ESTRIDE + lk0];
    unsigned* bsw = &Bs[lrow * ESTRIDE + lk0];
    int lg = lane >> 2, lt = lane & 3;

    float4 ra[4], rb[4];
#pragma unroll
    for (int q = 0; q < 4; q++) {
        ra[q] = *(const float4*)(Aptr + 4 * q);
        rb[q] = *(const float4*)(Wptr + 4 * q);
    }

    for (int kt = 0; kt < 256; kt += 32) {
#pragma unroll
        for (int q = 0; q < 4; q++) {
            *(uint4*)(asw + 4 * q) = f2tf4(ra[q]);
            *(uint4*)(bsw + 4 * q) = f2tf4(rb[q]);
        }
        __syncthreads();
        if (kt + 32 < 256) {
#pragma unroll
            for (int q = 0; q < 4; q++) {
                ra[q] = *(const float4*)(Aptr + kt + 32 + 4 * q);
                rb[q] = *(const float4*)(Wptr + kt + 32 + 4 * q);
            }
        }
#pragma unroll
        for (int k8 = 0; k8 < 4; k8++) {
            int kc = k8 * 8 + lt;
            unsigned af[2][4], bf[4][2];
#pragma unroll
            for (int mi = 0; mi < 2; mi++) {
                int r0 = warp_m + mi * 16 + lg;
                af[mi][0] = As[r0 * ESTRIDE + kc];
                af[mi][1] = As[(r0 + 8) * ESTRIDE + kc];
                af[mi][2] = As[r0 * ESTRIDE + kc + 4];
                af[mi][3] = As[(r0 + 8) * ESTRIDE + kc + 4];
            }
#pragma unroll
            for (int ni = 0; ni < 4; ni++) {
                int n0 = warp_n + ni * 8 + lg;
                bf[ni][0] = Bs[n0 * ESTRIDE + kc];
                bf[ni][1] = Bs[n0 * ESTRIDE + kc + 4];
            }
#pragma unroll
            for (int mi = 0; mi < 2; mi++)
#pragma unroll
                for (int ni = 0; ni < 4; ni++)
                    mma16n8k8(c[mi][ni][0], c[mi][ni][1], c[mi][ni][2], c[mi][ni][3],
                              af[mi][0], af[mi][1], af[mi][2], af[mi][3],
                              bf[ni][0], bf[ni][1]);
        }
        __syncthreads();
    }

#pragma unroll
    for (int mi = 0; mi < 2; mi++)
#pragma unroll
        for (int half = 0; half < 2; half++) {
            int m = mbase + warp_m + mi * 16 + lg + half * 8;
#pragma unroll
            for (int ni = 0; ni < 4; ni++) {
                int col = nbase + warp_n + ni * 8 + 2 * lt;
                *(float2*)&out[(size_t)m * 256 + col] =
                    make_float2(c[mi][ni][2 * half + 0], c[mi][ni][2 * half + 1]);
            }
        }
}

// ---------------- per-row LayerNorm on edges (in place) + dot with v -------
__global__ void ln_edge_kernel(float* __restrict__ e, const float* __restrict__ g,
                               const float* __restrict__ bt, const float* __restrict__ v,
                               float* __restrict__ dotv)
{
    int warp = threadIdx.x >> 5, lane = threadIdx.x & 31;
    int row = blockIdx.x * 8 + warp;
    float* rp = e + (size_t)row * 256;
    float x[8];
    float su = 0.f, sq = 0.f;
#pragma unroll
    for (int q = 0; q < 8; q++) {
        x[q] = rp[lane + q * 32];
        su += x[q]; sq += x[q] * x[q];
    }
#pragma unroll
    for (int o = 16; o; o >>= 1) {
        su += __shfl_xor_sync(0xffffffffu, su, o);
        sq += __shfl_xor_sync(0xffffffffu, sq, o);
    }
    float mean = su * (1.f / 256.f);
    float var = sq * (1.f / 256.f) - mean * mean;
    float inv = rsqrtf(var + LN_EPS);
    float dv = 0.f;
#pragma unroll
    for (int q = 0; q < 8; q++) {
        int c = lane + q * 32;
        float y = (x[q] - mean) * inv * g[c] + bt[c];
        rp[c] = y;
        dv += y * v[c];
    }
#pragma unroll
    for (int o = 16; o; o >>= 1) dv += __shfl_xor_sync(0xffffffffu, dv, o);
    if (lane == 0) dotv[row] = dv;
}

// ---------------- v = Wbp^T ub, w = Wfp^T ub, s = nodes·w (merged) ---------
__global__ void vws_kernel(const float* __restrict__ Wbp, const float* __restrict__ Wfp,
                           const float* __restrict__ ub, const float* __restrict__ nodes,
                           float* __restrict__ v, float* __restrict__ w,
                           float* __restrict__ s)
{
    __shared__ float ws[256];
    int k = threadIdx.x;
    float a = 0.f, b = 0.f;
    for (int c = 0; c < 256; c++) {
        float u = ub[c];
        a += u * Wbp[c * 256 + k];
        b += u * Wfp[c * 256 + k];
    }
    v[k] = a; w[k] = b;
    ws[k] = b;
    __syncthreads();
    float acc = 0.f;
    const float* rp = nodes + (size_t)k * 256;
    for (int c = 0; c < 256; c++) acc += rp[c] * ws[c];
    s[k] = acc;
}

// ---------------- attention + node update (LN fused) -----------------------
__global__ void __launch_bounds__(256)
attn_kernel(const float* __restrict__ dotv, const float* __restrict__ s,
            const float* __restrict__ nf, const float* __restrict__ mask,
            const float* __restrict__ nodes_old, const float* __restrict__ g,
            const float* __restrict__ bt, float* __restrict__ nodes_new)
{
    int bi = blockIdx.x;
    int b = bi >> 7, i = bi & 127;
    int t = threadIdx.x;
    __shared__ float sm_a[128];
    __shared__ float sred1[8], sred2[8];
    __shared__ float sm_m, sm_sum, sm_mean, sm_inv;

    if (t < 128) {
        int j = t;
        float mv = mask[b * 16384 + i * 128 + j];
        float r;
        if (mv > 0.f) {
            float dv = dotv[b * 16384 + j * 128 + i];
            r = dv + s[b * 128 + i] + s[b * 128 + j];
            r = r > 0.f ? r : ALPHA * r;
        } else {
            r = NEG_BIG;
        }
        sm_a[j] = r;
    }
    __syncthreads();
    if (t < 32) {
        float m = fmaxf(fmaxf(sm_a[t], sm_a[t + 32]), fmaxf(sm_a[t + 64], sm_a[t + 96]));
#pragma unroll
        for (int o = 16; o; o >>= 1) m = fmaxf(m, __shfl_xor_sync(0xffffffffu, m, o));
        if (t == 0) sm_m = m;
    }
    __syncthreads();
    if (t < 128) sm_a[t] = expf(sm_a[t] - sm_m);
    __syncthreads();
    if (t < 32) {
        float su = sm_a[t] + sm_a[t + 32] + sm_a[t + 64] + sm_a[t + 96];
#pragma unroll
        for (int o = 16; o; o >>= 1) su += __shfl_xor_sync(0xffffffffu, su, o);
        if (t == 0) sm_sum = su;
    }
    __syncthreads();
    float inv_sum = 1.f / sm_sum;

    int c = t;
    float acc = 0.f;
    const float* nfb = nf + (size_t)b * Nn * Cc + c;
#pragma unroll 4
    for (int j = 0; j < 128; j++) acc += sm_a[j] * nfb[(size_t)j * Cc];
    acc *= inv_sum;
    float h = (acc > 0.f ? acc : ALPHA * acc) + nodes_old[(size_t)(b * 128 + i) * 256 + c];

    int lane = t & 31, wp = t >> 5;
    float su = h, sq = h * h;
#pragma unroll
    for (int o = 16; o; o >>= 1) {
        su += __shfl_xor_sync(0xffffffffu, su, o);
        sq += __shfl_xor_sync(0xffffffffu, sq, o);
    }
    if (lane == 0) { sred1[wp] = su; sred2[wp] = sq; }
    __syncthreads();
    if (t == 0) {
        float S = 0.f, Q = 0.f;
#pragma unroll
        for (int w2 = 0; w2 < 8; w2++) { S += sred1[w2]; Q += sred2[w2]; }
        float mean = S * (1.f / 256.f);
        float var = Q * (1.f / 256.f) - mean * mean;
        sm_mean = mean;
        sm_inv = rsqrtf(var + LN_EPS);
    }
    __syncthreads();
    nodes_new[(size_t)(b * 128 + i) * 256 + c] = (h - sm_mean) * sm_inv * g[c] + bt[c];
}

// ---------------- edge logits: out[row,k] = e[row]·ecW[k] + ecb[k] ---------
__global__ void edge_logits_kernel(const float* __restrict__ e, const float* __restrict__ W,
                                   const float* __restrict__ bias, float* __restrict__ out)
{
    int warp = threadIdx.x >> 5, lane = threadIdx.x & 31;
    int row = blockIdx.x * 8 + warp;
    const float* rp = e + (size_t)row * 256;
    float x[8];
#pragma unroll
    for (int q = 0; q < 8; q++) x[q] = rp[lane + q * 32];
#pragma unroll
    for (int k = 0; k < KE_; k++) {
        float acc = 0.f;
#pragma unroll
        for (int q = 0; q < 8; q++) acc += x[q] * W[k * 256 + lane + q * 32];
#pragma unroll
        for (int o = 16; o; o >>= 1) acc += __shfl_xor_sync(0xffffffffu, acc, o);
        if (lane == 0) out[(size_t)row * KE_ + k] = acc + bias[k];
    }
}

// ---------------- host ------------------------------------------------------
extern "C" void kernel_launch(void* const* d_in, const int* in_sizes, int n_in,
                              void* d_out, int out_size)
{
    const float* nodes_in = (const float*)d_in[0];
    const float* edges_in = (const float*)d_in[1];
    const float* adj      = (const float*)d_in[2];
    const float* pnW = (const float*)d_in[3];
    const float* pnb = (const float*)d_in[4];
    const float* peW = (const float*)d_in[5];
    const float* peb = (const float*)d_in[6];
    const float* Wb  = (const float*)d_in[7];
    const float* Wbp = (const float*)d_in[8];
    const float* Wfp = (const float*)d_in[9];
    const float* ub  = (const float*)d_in[10];
    const float* Wf  = (const float*)d_in[11];
    const float* eln_g = (const float*)d_in[12];
    const float* eln_b = (const float*)d_in[13];
    const float* nln_g = (const float*)d_in[14];
    const float* nln_b = (const float*)d_in[15];
    const float* ncW = (const float*)d_in[16];
    const float* ncb = (const float*)d_in[17];
    const float* ecW = (const float*)d_in[18];
    const float* ecb = (const float*)d_in[19];

    float *eA, *eB, *n0, *n1, *ai_, *aj_, *nf_, *s_, *v_, *w_, *dv_;
    cudaGetSymbolAddress((void**)&eA, g_eA);
    cudaGetSymbolAddress((void**)&eB, g_eB);
    cudaGetSymbolAddress((void**)&n0, g_n0);
    cudaGetSymbolAddress((void**)&n1, g_n1);
    cudaGetSymbolAddress((void**)&ai_, g_ai);
    cudaGetSymbolAddress((void**)&aj_, g_aj);
    cudaGetSymbolAddress((void**)&nf_, g_nf);
    cudaGetSymbolAddress((void**)&s_, g_s);
    cudaGetSymbolAddress((void**)&v_, g_v);
    cudaGetSymbolAddress((void**)&w_, g_w);
    cudaGetSymbolAddress((void**)&dv_, g_dotv);

    float* out = (float*)d_out;
    float* out_nodes = out;
    float* out_edges = out + NODES_SZ;

    // ping-pong schedule; layer 2 writes land directly in d_out (no copies)
    float* ebuf[4] = {eA, eB, eA, out_edges};
    float* nbuf[4] = {n0, n1, n0, out_nodes};

    dim3 bs(16, 16);

    // initial projections
    gemm_small<<<dim3(16, 16), bs>>>(nodes_in, pnW, pnb, nbuf[0], 256, 256, 128, 128);
    edge_mma<0><<<dim3(2, 256), 256>>>(edges_in, peW, 64, 64, peb,
                                       nullptr, nullptr, nullptr, ebuf[0]);

    for (int l = 0; l < 3; l++) {
        const float* Wb_l  = Wb  + (size_t)l * 256 * 768;
        const float* Wbp_l = Wbp + (size_t)l * 65536;
        const float* Wfp_l = Wfp + (size_t)l * 65536;
        const float* ub_l  = ub  + l * 256;
        const float* Wf_l  = Wf  + (size_t)l * 65536;
        float* ecur = ebuf[l]; float* enxt = ebuf[l + 1];
        float* ncur = nbuf[l]; float* nnxt = nbuf[l + 1];

        vws_kernel<<<1, 256>>>(Wbp_l, Wfp_l, ub_l, ncur, v_, w_, s_);
        node3_mma<<<dim3(4, 4, 3), 128>>>(ncur, Wb_l, Wf_l, ai_, aj_, nf_);

        edge_mma<1><<<dim3(2, 256), 256>>>(ecur, Wb_l + 256, 256, 768, nullptr,
                                           ai_, aj_, adj, enxt);
        ln_edge_kernel<<<4096, 256>>>(enxt, eln_g + l * 256, eln_b + l * 256, v_, dv_);
        attn_kernel<<<256, 256>>>(dv_, s_, nf_, adj, ncur,
                                  nln_g + l * 256, nln_b + l * 256, nnxt);
    }

    // final heads read directly from d_out regions
    gemm_small<<<dim3(7, 16), bs>>>(nbuf[3], ncW, ncb, out + NODES_SZ + EDGES_SZ,
                                    256, KN_, 256, 256);
    edge_logits_kernel<<<4096, 256>>>(ebuf[3], ecW, ecb,
                                      out + NODES_SZ + EDGES_SZ + 256 * KN_);
}

// round 8
// speedup vs baseline: 1.4288x; 1.4288x over previous
#include <cuda_runtime.h>

#define Bb 2
#define Nn 128
#define Cc 256
#define BN2 (Bb*Nn*Nn)        // 32768 edge rows
#define NODES_SZ (Bb*Nn*Cc)   // 65536
#define EDGES_SZ (BN2*Cc)     // 8388608
#define KN_ 101
#define KE_ 7
#define ALPHA 0.2f
#define LN_EPS 1e-5f
#define NEG_BIG (-1e30f)

// ---------------- scratch (device globals: allocation-free) ----------------
__device__ float g_eA[EDGES_SZ];
__device__ float g_eB[EDGES_SZ];
__device__ float g_n0[NODES_SZ];
__device__ float g_n1[NODES_SZ];
__device__ float g_ai[NODES_SZ];
__device__ float g_aj[NODES_SZ];
__device__ float g_nf[NODES_SZ];
__device__ float g_s[Bb*Nn];
__device__ float g_v[Cc];
__device__ float g_w[Cc];
__device__ float g_dotv[BN2];

// ---------------- tf32 helpers ---------------------------------------------
__device__ __forceinline__ unsigned f2tf(float f)
{
    unsigned r;
    asm("cvt.rna.tf32.f32 %0, %1;" : "=r"(r) : "f"(f));
    return r;
}
__device__ __forceinline__ uint4 f2tf4(float4 v)
{
    return make_uint4(f2tf(v.x), f2tf(v.y), f2tf(v.z), f2tf(v.w));
}
__device__ __forceinline__ void mma16n8k8(float& c0, float& c1, float& c2, float& c3,
                                          unsigned a0, unsigned a1, unsigned a2, unsigned a3,
                                          unsigned b0, unsigned b1)
{
    asm volatile("mma.sync.aligned.m16n8k8.row.col.f32.tf32.tf32.f32 "
                 "{%0,%1,%2,%3}, {%4,%5,%6,%7}, {%8,%9}, {%0,%1,%2,%3};"
                 : "+f"(c0), "+f"(c1), "+f"(c2), "+f"(c3)
                 : "r"(a0), "r"(a1), "r"(a2), "r"(a3), "r"(b0), "r"(b1));
}

// ---------------- small generic GEMM: out[m,n] = A[m,:]·W[n,:] + bias ------
__global__ void gemm_small(const float* __restrict__ A, const float* __restrict__ W,
                           const float* __restrict__ bias, float* __restrict__ out,
                           int M, int N, int K, int ldw)
{
    __shared__ float As[16][16];
    __shared__ float Ws[16][17];
    int tx = threadIdx.x, ty = threadIdx.y;
    int m = blockIdx.y * 16 + ty;
    int n = blockIdx.x * 16 + tx;
    float acc = 0.f;
    for (int k0 = 0; k0 < K; k0 += 16) {
        As[ty][tx] = (m < M) ? A[m * K + k0 + tx] : 0.f;
        int nn = blockIdx.x * 16 + ty;
        Ws[ty][tx] = (nn < N) ? W[(size_t)nn * ldw + k0 + tx] : 0.f;
        __syncthreads();
#pragma unroll
        for (int kk = 0; kk < 16; kk++) acc += As[ty][kk] * Ws[tx][kk];
        __syncthreads();
    }
    if (m < M && n < N) {
        float b = bias ? bias[n] : 0.f;
        out[m * N + n] = acc + b;
    }
}

// ---------------- edge GEMM, tf32, software-pipelined ----------------------
// 128x128 tile, 8 warps of 64x32, BK=32. NO min-blocks bound: regs must float
// (~160) so the staging registers do NOT spill. 1 CTA/SM, 8 warps is enough.
// MODE 0: out = A@W^T + bias[n]
// MODE 1: out = lrelu(A@W^T + ai[b,i,n] + aj[b,j,n]) * mask[m] + A[m,n]
#define ESTRIDE 36
template<int MODE>
__global__ void __launch_bounds__(256)
edge_mma(const float* __restrict__ A, const float* __restrict__ W,
         int K, int ldw, const float* __restrict__ bias,
         const float* __restrict__ ai, const float* __restrict__ aj,
         const float* __restrict__ mask, float* __restrict__ out)
{
    __shared__ unsigned As[128 * ESTRIDE];
    __shared__ unsigned Bs[128 * ESTRIDE];
    int tid = threadIdx.x;
    int lane = tid & 31, wid = tid >> 5;
    int warp_m = (wid & 1) * 64;
    int warp_n = (wid >> 1) * 32;
    int mbase = blockIdx.y * 128;
    int nbase = blockIdx.x * 128;

    float c[4][4][4];
#pragma unroll
    for (int mi = 0; mi < 4; mi++)
#pragma unroll
        for (int ni = 0; ni < 4; ni++)
#pragma unroll
            for (int q = 0; q < 4; q++) c[mi][ni][q] = 0.f;

    int lrow = tid >> 1;
    int lk0 = (tid & 1) * 16;
    const float* Aptr = A + (size_t)(mbase + lrow) * K + lk0;
    const float* Wptr = W + (size_t)(nbase + lrow) * ldw + lk0;
    unsigned* asw = &As[lrow * ESTRIDE + lk0];
    unsigned* bsw = &Bs[lrow * ESTRIDE + lk0];
    int lg = lane >> 2, lt = lane & 3;

    // prologue: stage k-tile 0 in registers
    float4 ra[4], rb[4];
#pragma unroll
    for (int q = 0; q < 4; q++) {
        ra[q] = *(const float4*)(Aptr + 4 * q);
        rb[q] = *(const float4*)(Wptr + 4 * q);
    }

    for (int kt = 0; kt < K; kt += 32) {
        // drain staged regs to smem
#pragma unroll
        for (int q = 0; q < 4; q++) {
            *(uint4*)(asw + 4 * q) = f2tf4(ra[q]);
            *(uint4*)(bsw + 4 * q) = f2tf4(rb[q]);
        }
        __syncthreads();
        // issue next-stage loads; latency hidden behind the MMAs below
        if (kt + 32 < K) {
#pragma unroll
            for (int q = 0; q < 4; q++) {
                ra[q] = *(const float4*)(Aptr + kt + 32 + 4 * q);
                rb[q] = *(const float4*)(Wptr + kt + 32 + 4 * q);
            }
        }
#pragma unroll
        for (int k8 = 0; k8 < 4; k8++) {
            int kc = k8 * 8 + lt;
            unsigned af[4][4], bf[4][2];
#pragma unroll
            for (int mi = 0; mi < 4; mi++) {
                int r0 = warp_m + mi * 16 + lg;
                af[mi][0] = As[r0 * ESTRIDE + kc];
                af[mi][1] = As[(r0 + 8) * ESTRIDE + kc];
                af[mi][2] = As[r0 * ESTRIDE + kc + 4];
                af[mi][3] = As[(r0 + 8) * ESTRIDE + kc + 4];
            }
#pragma unroll
            for (int ni = 0; ni < 4; ni++) {
                int n0 = warp_n + ni * 8 + lg;
                bf[ni][0] = Bs[n0 * ESTRIDE + kc];
                bf[ni][1] = Bs[n0 * ESTRIDE + kc + 4];
            }
#pragma unroll
            for (int mi = 0; mi < 4; mi++)
#pragma unroll
                for (int ni = 0; ni < 4; ni++)
                    mma16n8k8(c[mi][ni][0], c[mi][ni][1], c[mi][ni][2], c[mi][ni][3],
                              af[mi][0], af[mi][1], af[mi][2], af[mi][3],
                              bf[ni][0], bf[ni][1]);
        }
        __syncthreads();
    }

    // epilogue
#pragma unroll
    for (int mi = 0; mi < 4; mi++) {
#pragma unroll
        for (int half = 0; half < 2; half++) {
            int m = mbase + warp_m + mi * 16 + lg + half * 8;
            int b = m >> 14;
            int i = (m >> 7) & 127;
            int j = m & 127;
            float mv = 0.f;
            const float* aip = nullptr;
            const float* ajp = nullptr;
            if (MODE == 1) {
                mv = mask[m];
                aip = &ai[(size_t)((b << 7) + i) * 256];
                ajp = &aj[(size_t)((b << 7) + j) * 256];
            }
#pragma unroll
            for (int ni = 0; ni < 4; ni++) {
                int col = nbase + warp_n + ni * 8 + 2 * lt;
                float v0 = c[mi][ni][2 * half + 0];
                float v1 = c[mi][ni][2 * half + 1];
                if (MODE == 0) {
                    float2 bv = *(const float2*)&bias[col];
                    v0 += bv.x; v1 += bv.y;
                } else {
                    float2 av2 = *(const float2*)&aip[col];
                    float2 aj2 = *(const float2*)&ajp[col];
                    float2 rs2 = *(const float2*)&A[(size_t)m * 256 + col];
                    v0 += av2.x + aj2.x;
                    v1 += av2.y + aj2.y;
                    v0 = (v0 > 0.f ? v0 : ALPHA * v0) * mv + rs2.x;
                    v1 = (v1 > 0.f ? v1 : ALPHA * v1) * mv + rs2.y;
                }
                *(float2*)&out[(size_t)m * 256 + col] = make_float2(v0, v1);
            }
        }
    }
}

// ---------------- node GEMMs: 64x64 tiles, 48 blocks, pipelined ------------
// z=0 -> ai (Wb1, ldw 768), z=1 -> aj (Wb3, ldw 768), z=2 -> nf (Wf, ldw 256)
__global__ void __launch_bounds__(128)
node3_mma(const float* __restrict__ A, const float* __restrict__ Wb_l,
          const float* __restrict__ Wf_l,
          float* __restrict__ ai, float* __restrict__ aj, float* __restrict__ nf)
{
    __shared__ unsigned As[64 * ESTRIDE];
    __shared__ unsigned Bs[64 * ESTRIDE];
    int z = blockIdx.z;
    const float* W = (z == 0) ? Wb_l : (z == 1) ? (Wb_l + 512) : Wf_l;
    int ldw = (z == 2) ? 256 : 768;
    float* out = (z == 0) ? ai : (z == 1) ? aj : nf;

    int tid = threadIdx.x;
    int lane = tid & 31, wid = tid >> 5;          // 4 warps
    int warp_m = (wid & 1) * 32;
    int warp_n = (wid >> 1) * 32;
    int mbase = blockIdx.y * 64;
    int nbase = blockIdx.x * 64;

    float c[2][4][4];
#pragma unroll
    for (int mi = 0; mi < 2; mi++)
#pragma unroll
        for (int ni = 0; ni < 4; ni++)
#pragma unroll
            for (int q = 0; q < 4; q++) c[mi][ni][q] = 0.f;

    int lrow = tid >> 1;               // 0..63
    int lk0 = (tid & 1) * 16;
    const float* Aptr = A + (size_t)(mbase + lrow) * 256 + lk0;
    const float* Wptr = W + (size_t)(nbase + lrow) * ldw + lk0;
    unsigned* asw = &As[lrow * ESTRIDE + lk0];
    unsigned* bsw = &Bs[lrow * ESTRIDE + lk0];
    int lg = lane >> 2, lt = lane & 3;

    float4 ra[4], rb[4];
#pragma unroll
    for (int q = 0; q < 4; q++) {
        ra[q] = *(const float4*)(Aptr + 4 * q);
        rb[q] = *(const float4*)(Wptr + 4 * q);
    }

    for (int kt = 0; kt < 256; kt += 32) {
#pragma unroll
        for (int q = 0; q < 4; q++) {
            *(uint4*)(asw + 4 * q) = f2tf4(ra[q]);
            *(uint4*)(bsw + 4 * q) = f2tf4(rb[q]);
        }
        __syncthreads();
        if (kt + 32 < 256) {
#pragma unroll
            for (int q = 0; q < 4; q++) {
                ra[q] = *(const float4*)(Aptr + kt + 32 + 4 * q);
                rb[q] = *(const float4*)(Wptr + kt + 32 + 4 * q);
            }
        }
#pragma unroll
        for (int k8 = 0; k8 < 4; k8++) {
            int kc = k8 * 8 + lt;
            unsigned af[2][4], bf[4][2];
#pragma unroll
            for (int mi = 0; mi < 2; mi++) {
                int r0 = warp_m + mi * 16 + lg;
                af[mi][0] = As[r0 * ESTRIDE + kc];
                af[mi][1] = As[(r0 + 8) * ESTRIDE + kc];
                af[mi][2] = As[r0 * ESTRIDE + kc + 4];
                af[mi][3] = As[(r0 + 8) * ESTRIDE + kc + 4];
            }
#pragma unroll
            for (int ni = 0; ni < 4; ni++) {
                int n0 = warp_n + ni * 8 + lg;
                bf[ni][0] = Bs[n0 * ESTRIDE + kc];
                bf[ni][1] = Bs[n0 * ESTRIDE + kc + 4];
            }
#pragma unroll
            for (int mi = 0; mi < 2; mi++)
#pragma unroll
                for (int ni = 0; ni < 4; ni++)
                    mma16n8k8(c[mi][ni][0], c[mi][ni][1], c[mi][ni][2], c[mi][ni][3],
                              af[mi][0], af[mi][1], af[mi][2], af[mi][3],
                              bf[ni][0], bf[ni][1]);
        }
        __syncthreads();
    }

#pragma unroll
    for (int mi = 0; mi < 2; mi++)
#pragma unroll
        for (int half = 0; half < 2; half++) {
            int m = mbase + warp_m + mi * 16 + lg + half * 8;
#pragma unroll
            for (int ni = 0; ni < 4; ni++) {
                int col = nbase + warp_n + ni * 8 + 2 * lt;
                *(float2*)&out[(size_t)m * 256 + col] =
                    make_float2(c[mi][ni][2 * half + 0], c[mi][ni][2 * half + 1]);
            }
        }
}

// ---------------- per-row LayerNorm on edges (in place) + dot with v -------
__global__ void ln_edge_kernel(float* __restrict__ e, const float* __restrict__ g,
                               const float* __restrict__ bt, const float* __restrict__ v,
                               float* __restrict__ dotv)
{
    int warp = threadIdx.x >> 5, lane = threadIdx.x & 31;
    int row = blockIdx.x * 8 + warp;
    float* rp = e + (size_t)row * 256;
    float x[8];
    float su = 0.f, sq = 0.f;
#pragma unroll
    for (int q = 0; q < 8; q++) {
        x[q] = rp[lane + q * 32];
        su += x[q]; sq += x[q] * x[q];
    }
#pragma unroll
    for (int o = 16; o; o >>= 1) {
        su += __shfl_xor_sync(0xffffffffu, su, o);
        sq += __shfl_xor_sync(0xffffffffu, sq, o);
    }
    float mean = su * (1.f / 256.f);
    float var = sq * (1.f / 256.f) - mean * mean;
    float inv = rsqrtf(var + LN_EPS);
    float dv = 0.f;
#pragma unroll
    for (int q = 0; q < 8; q++) {
        int c = lane + q * 32;
        float y = (x[q] - mean) * inv * g[c] + bt[c];
        rp[c] = y;
        dv += y * v[c];
    }
#pragma unroll
    for (int o = 16; o; o >>= 1) dv += __shfl_xor_sync(0xffffffffu, dv, o);
    if (lane == 0) dotv[row] = dv;
}

// ---------------- v = Wbp^T ub, w = Wfp^T ub, s = nodes·w (merged) ---------
__global__ void vws_kernel(const float* __restrict__ Wbp, const float* __restrict__ Wfp,
                           const float* __restrict__ ub, const float* __restrict__ nodes,
                           float* __restrict__ v, float* __restrict__ w,
                           float* __restrict__ s)
{
    __shared__ float ws[256];
    int k = threadIdx.x;
    float a = 0.f, b = 0.f;
    for (int c = 0; c < 256; c++) {
        float u = ub[c];
        a += u * Wbp[c * 256 + k];
        b += u * Wfp[c * 256 + k];
    }
    v[k] = a; w[k] = b;
    ws[k] = b;
    __syncthreads();
    float acc = 0.f;
    const float* rp = nodes + (size_t)k * 256;
    for (int c = 0; c < 256; c++) acc += rp[c] * ws[c];
    s[k] = acc;
}

// ---------------- attention + node update (LN fused) -----------------------
__global__ void __launch_bounds__(256)
attn_kernel(const float* __restrict__ dotv, const float* __restrict__ s,
            const float* __restrict__ nf, const float* __restrict__ mask,
            const float* __restrict__ nodes_old, const float* __restrict__ g,
            const float* __restrict__ bt, float* __restrict__ nodes_new)
{
    int bi = blockIdx.x;
    int b = bi >> 7, i = bi & 127;
    int t = threadIdx.x;
    __shared__ float sm_a[128];
    __shared__ float sred1[8], sred2[8];
    __shared__ float sm_m, sm_sum, sm_mean, sm_inv;

    if (t < 128) {
        int j = t;
        float mv = mask[b * 16384 + i * 128 + j];
        float r;
        if (mv > 0.f) {
            float dv = dotv[b * 16384 + j * 128 + i];
            r = dv + s[b * 128 + i] + s[b * 128 + j];
            r = r > 0.f ? r : ALPHA * r;
        } else {
            r = NEG_BIG;
        }
        sm_a[j] = r;
    }
    __syncthreads();
    if (t < 32) {
        float m = fmaxf(fmaxf(sm_a[t], sm_a[t + 32]), fmaxf(sm_a[t + 64], sm_a[t + 96]));
#pragma unroll
        for (int o = 16; o; o >>= 1) m = fmaxf(m, __shfl_xor_sync(0xffffffffu, m, o));
        if (t == 0) sm_m = m;
    }
    __syncthreads();
    if (t < 128) sm_a[t] = expf(sm_a[t] - sm_m);
    __syncthreads();
    if (t < 32) {
        float su = sm_a[t] + sm_a[t + 32] + sm_a[t + 64] + sm_a[t + 96];
#pragma unroll
        for (int o = 16; o; o >>= 1) su += __shfl_xor_sync(0xffffffffu, su, o);
        if (t == 0) sm_sum = su;
    }
    __syncthreads();
    float inv_sum = 1.f / sm_sum;

    int c = t;
    float acc = 0.f;
    const float* nfb = nf + (size_t)b * Nn * Cc + c;
#pragma unroll 4
    for (int j = 0; j < 128; j++) acc += sm_a[j] * nfb[(size_t)j * Cc];
    acc *= inv_sum;
    float h = (acc > 0.f ? acc : ALPHA * acc) + nodes_old[(size_t)(b * 128 + i) * 256 + c];

    int lane = t & 31, wp = t >> 5;
    float su = h, sq = h * h;
#pragma unroll
    for (int o = 16; o; o >>= 1) {
        su += __shfl_xor_sync(0xffffffffu, su, o);
        sq += __shfl_xor_sync(0xffffffffu, sq, o);
    }
    if (lane == 0) { sred1[wp] = su; sred2[wp] = sq; }
    __syncthreads();
    if (t == 0) {
        float S = 0.f, Q = 0.f;
#pragma unroll
        for (int w2 = 0; w2 < 8; w2++) { S += sred1[w2]; Q += sred2[w2]; }
        float mean = S * (1.f / 256.f);
        float var = Q * (1.f / 256.f) - mean * mean;
        sm_mean = mean;
        sm_inv = rsqrtf(var + LN_EPS);
    }
    __syncthreads();
    nodes_new[(size_t)(b * 128 + i) * 256 + c] = (h - sm_mean) * sm_inv * g[c] + bt[c];
}

// ---------------- edge logits: out[row,k] = e[row]·ecW[k] + ecb[k] ---------
__global__ void edge_logits_kernel(const float* __restrict__ e, const float* __restrict__ W,
                                   const float* __restrict__ bias, float* __restrict__ out)
{
    int warp = threadIdx.x >> 5, lane = threadIdx.x & 31;
    int row = blockIdx.x * 8 + warp;
    const float* rp = e + (size_t)row * 256;
    float x[8];
#pragma unroll
    for (int q = 0; q < 8; q++) x[q] = rp[lane + q * 32];
#pragma unroll
    for (int k = 0; k < KE_; k++) {
        float acc = 0.f;
#pragma unroll
        for (int q = 0; q < 8; q++) acc += x[q] * W[k * 256 + lane + q * 32];
#pragma unroll
        for (int o = 16; o; o >>= 1) acc += __shfl_xor_sync(0xffffffffu, acc, o);
        if (lane == 0) out[(size_t)row * KE_ + k] = acc + bias[k];
    }
}

// ---------------- host ------------------------------------------------------
extern "C" void kernel_launch(void* const* d_in, const int* in_sizes, int n_in,
                              void* d_out, int out_size)
{
    const float* nodes_in = (const float*)d_in[0];
    const float* edges_in = (const float*)d_in[1];
    const float* adj      = (const float*)d_in[2];
    const float* pnW = (const float*)d_in[3];
    const float* pnb = (const float*)d_in[4];
    const float* peW = (const float*)d_in[5];
    const float* peb = (const float*)d_in[6];
    const float* Wb  = (const float*)d_in[7];
    const float* Wbp = (const float*)d_in[8];
    const float* Wfp = (const float*)d_in[9];
    const float* ub  = (const float*)d_in[10];
    const float* Wf  = (const float*)d_in[11];
    const float* eln_g = (const float*)d_in[12];
    const float* eln_b = (const float*)d_in[13];
    const float* nln_g = (const float*)d_in[14];
    const float* nln_b = (const float*)d_in[15];
    const float* ncW = (const float*)d_in[16];
    const float* ncb = (const float*)d_in[17];
    const float* ecW = (const float*)d_in[18];
    const float* ecb = (const float*)d_in[19];

    float *eA, *eB, *n0, *n1, *ai_, *aj_, *nf_, *s_, *v_, *w_, *dv_;
    cudaGetSymbolAddress((void**)&eA, g_eA);
    cudaGetSymbolAddress((void**)&eB, g_eB);
    cudaGetSymbolAddress((void**)&n0, g_n0);
    cudaGetSymbolAddress((void**)&n1, g_n1);
    cudaGetSymbolAddress((void**)&ai_, g_ai);
    cudaGetSymbolAddress((void**)&aj_, g_aj);
    cudaGetSymbolAddress((void**)&nf_, g_nf);
    cudaGetSymbolAddress((void**)&s_, g_s);
    cudaGetSymbolAddress((void**)&v_, g_v);
    cudaGetSymbolAddress((void**)&w_, g_w);
    cudaGetSymbolAddress((void**)&dv_, g_dotv);

    float* out = (float*)d_out;
    float* out_nodes = out;
    float* out_edges = out + NODES_SZ;

    // ping-pong schedule; layer 2 writes land directly in d_out (no copies)
    float* ebuf[4] = {eA, eB, eA, out_edges};
    float* nbuf[4] = {n0, n1, n0, out_nodes};

    dim3 bs(16, 16);

    // initial projections
    gemm_small<<<dim3(16, 16), bs>>>(nodes_in, pnW, pnb, nbuf[0], 256, 256, 128, 128);
    edge_mma<0><<<dim3(2, 256), 256>>>(edges_in, peW, 64, 64, peb,
                                       nullptr, nullptr, nullptr, ebuf[0]);

    for (int l = 0; l < 3; l++) {
        const float* Wb_l  = Wb  + (size_t)l * 256 * 768;
        const float* Wbp_l = Wbp + (size_t)l * 65536;
        const float* Wfp_l = Wfp + (size_t)l * 65536;
        const float* ub_l  = ub  + l * 256;
        const float* Wf_l  = Wf  + (size_t)l * 65536;
        float* ecur = ebuf[l]; float* enxt = ebuf[l + 1];
        float* ncur = nbuf[l]; float* nnxt = nbuf[l + 1];

        vws_kernel<<<1, 256>>>(Wbp_l, Wfp_l, ub_l, ncur, v_, w_, s_);
        node3_mma<<<dim3(4, 4, 3), 128>>>(ncur, Wb_l, Wf_l, ai_, aj_, nf_);

        edge_mma<1><<<dim3(2, 256), 256>>>(ecur, Wb_l + 256, 256, 768, nullptr,
                                           ai_, aj_, adj, enxt);
        ln_edge_kernel<<<4096, 256>>>(enxt, eln_g + l * 256, eln_b + l * 256, v_, dv_);
        attn_kernel<<<256, 256>>>(dv_, s_, nf_, adj, ncur,
                                  nln_g + l * 256, nln_b + l * 256, nnxt);
    }

    // final heads read directly from d_out regions
    gemm_small<<<dim3(7, 16), bs>>>(nbuf[3], ncW, ncb, out + NODES_SZ + EDGES_SZ,
                                    256, KN_, 256, 256);
    edge_logits_kernel<<<4096, 256>>>(ebuf[3], ecW, ecb,
                                      out + NODES_SZ + EDGES_SZ + 256 * KN_);
}

// round 9
// speedup vs baseline: 1.4443x; 1.0108x over previous
#include <cuda_runtime.h>

#define Bb 2
#define Nn 128
#define Cc 256
#define BN2 (Bb*Nn*Nn)        // 32768 edge rows
#define NODES_SZ (Bb*Nn*Cc)   // 65536
#define EDGES_SZ (BN2*Cc)     // 8388608
#define KN_ 101
#define KE_ 7
#define ALPHA 0.2f
#define LN_EPS 1e-5f
#define NEG_BIG (-1e30f)

// ---------------- scratch (device globals: allocation-free) ----------------
__device__ float g_eA[EDGES_SZ];
__device__ float g_eB[EDGES_SZ];
__device__ float g_n0[NODES_SZ];
__device__ float g_n1[NODES_SZ];
__device__ float g_ai[NODES_SZ];
__device__ float g_aj[NODES_SZ];
__device__ float g_nf[NODES_SZ];
__device__ float g_s[Bb*Nn];
__device__ float g_v[Cc];
__device__ float g_w[Cc];
__device__ float g_dotv[BN2];

// ---------------- tf32 helpers ---------------------------------------------
__device__ __forceinline__ unsigned f2tf(float f)
{
    unsigned r;
    asm("cvt.rna.tf32.f32 %0, %1;" : "=r"(r) : "f"(f));
    return r;
}
__device__ __forceinline__ uint4 f2tf4(float4 v)
{
    return make_uint4(f2tf(v.x), f2tf(v.y), f2tf(v.z), f2tf(v.w));
}
__device__ __forceinline__ void mma16n8k8(float& c0, float& c1, float& c2, float& c3,
                                          unsigned a0, unsigned a1, unsigned a2, unsigned a3,
                                          unsigned b0, unsigned b1)
{
    asm volatile("mma.sync.aligned.m16n8k8.row.col.f32.tf32.tf32.f32 "
                 "{%0,%1,%2,%3}, {%4,%5,%6,%7}, {%8,%9}, {%0,%1,%2,%3};"
                 : "+f"(c0), "+f"(c1), "+f"(c2), "+f"(c3)
                 : "r"(a0), "r"(a1), "r"(a2), "r"(a3), "r"(b0), "r"(b1));
}

// ---------------- small generic GEMM: out[m,n] = A[m,:]·W[n,:] + bias ------
__global__ void gemm_small(const float* __restrict__ A, const float* __restrict__ W,
                           const float* __restrict__ bias, float* __restrict__ out,
                           int M, int N, int K, int ldw)
{
    __shared__ float As[16][16];
    __shared__ float Ws[16][17];
    int tx = threadIdx.x, ty = threadIdx.y;
    int m = blockIdx.y * 16 + ty;
    int n = blockIdx.x * 16 + tx;
    float acc = 0.f;
    for (int k0 = 0; k0 < K; k0 += 16) {
        As[ty][tx] = (m < M) ? A[m * K + k0 + tx] : 0.f;
        int nn = blockIdx.x * 16 + ty;
        Ws[ty][tx] = (nn < N) ? W[(size_t)nn * ldw + k0 + tx] : 0.f;
        __syncthreads();
#pragma unroll
        for (int kk = 0; kk < 16; kk++) acc += As[ty][kk] * Ws[tx][kk];
        __syncthreads();
    }
    if (m < M && n < N) {
        float b = bias ? bias[n] : 0.f;
        out[m * N + n] = acc + b;
    }
}

// ---------------- edge projection GEMM (K=64), tf32, pipelined -------------
#define ESTRIDE 36
__global__ void __launch_bounds__(256)
edge_proj_mma(const float* __restrict__ A, const float* __restrict__ W,
              int K, int ldw, const float* __restrict__ bias, float* __restrict__ out)
{
    __shared__ unsigned As[128 * ESTRIDE];
    __shared__ unsigned Bs[128 * ESTRIDE];
    int tid = threadIdx.x;
    int lane = tid & 31, wid = tid >> 5;
    int warp_m = (wid & 1) * 64;
    int warp_n = (wid >> 1) * 32;
    int mbase = blockIdx.y * 128;
    int nbase = blockIdx.x * 128;

    float c[4][4][4];
#pragma unroll
    for (int mi = 0; mi < 4; mi++)
#pragma unroll
        for (int ni = 0; ni < 4; ni++)
#pragma unroll
            for (int q = 0; q < 4; q++) c[mi][ni][q] = 0.f;

    int lrow = tid >> 1;
    int lk0 = (tid & 1) * 16;
    const float* Aptr = A + (size_t)(mbase + lrow) * K + lk0;
    const float* Wptr = W + (size_t)(nbase + lrow) * ldw + lk0;
    unsigned* asw = &As[lrow * ESTRIDE + lk0];
    unsigned* bsw = &Bs[lrow * ESTRIDE + lk0];
    int lg = lane >> 2, lt = lane & 3;

    float4 ra[4], rb[4];
#pragma unroll
    for (int q = 0; q < 4; q++) {
        ra[q] = *(const float4*)(Aptr + 4 * q);
        rb[q] = *(const float4*)(Wptr + 4 * q);
    }

    for (int kt = 0; kt < K; kt += 32) {
#pragma unroll
        for (int q = 0; q < 4; q++) {
            *(uint4*)(asw + 4 * q) = f2tf4(ra[q]);
            *(uint4*)(bsw + 4 * q) = f2tf4(rb[q]);
        }
        __syncthreads();
        if (kt + 32 < K) {
#pragma unroll
            for (int q = 0; q < 4; q++) {
                ra[q] = *(const float4*)(Aptr + kt + 32 + 4 * q);
                rb[q] = *(const float4*)(Wptr + kt + 32 + 4 * q);
            }
        }
#pragma unroll
        for (int k8 = 0; k8 < 4; k8++) {
            int kc = k8 * 8 + lt;
            unsigned af[4][4], bf[4][2];
#pragma unroll
            for (int mi = 0; mi < 4; mi++) {
                int r0 = warp_m + mi * 16 + lg;
                af[mi][0] = As[r0 * ESTRIDE + kc];
                af[mi][1] = As[(r0 + 8) * ESTRIDE + kc];
                af[mi][2] = As[r0 * ESTRIDE + kc + 4];
                af[mi][3] = As[(r0 + 8) * ESTRIDE + kc + 4];
            }
#pragma unroll
            for (int ni = 0; ni < 4; ni++) {
                int n0 = warp_n + ni * 8 + lg;
                bf[ni][0] = Bs[n0 * ESTRIDE + kc];
                bf[ni][1] = Bs[n0 * ESTRIDE + kc + 4];
            }
#pragma unroll
            for (int mi = 0; mi < 4; mi++)
#pragma unroll
                for (int ni = 0; ni < 4; ni++)
                    mma16n8k8(c[mi][ni][0], c[mi][ni][1], c[mi][ni][2], c[mi][ni][3],
                              af[mi][0], af[mi][1], af[mi][2], af[mi][3],
                              bf[ni][0], bf[ni][1]);
        }
        __syncthreads();
    }

#pragma unroll
    for (int mi = 0; mi < 4; mi++)
#pragma unroll
        for (int half = 0; half < 2; half++) {
            int m = mbase + warp_m + mi * 16 + lg + half * 8;
#pragma unroll
            for (int ni = 0; ni < 4; ni++) {
                int col = nbase + warp_n + ni * 8 + 2 * lt;
                float2 bv = *(const float2*)&bias[col];
                *(float2*)&out[(size_t)m * 256 + col] =
                    make_float2(c[mi][ni][2 * half + 0] + bv.x,
                                c[mi][ni][2 * half + 1] + bv.y);
            }
        }
}

// ---------------- node GEMMs: 64x64 tiles, 48 blocks, pipelined ------------
__global__ void __launch_bounds__(128)
node3_mma(const float* __restrict__ A, const float* __restrict__ Wb_l,
          const float* __restrict__ Wf_l,
          float* __restrict__ ai, float* __restrict__ aj, float* __restrict__ nf)
{
    __shared__ unsigned As[64 * ESTRIDE];
    __shared__ unsigned Bs[64 * ESTRIDE];
    int z = blockIdx.z;
    const float* W = (z == 0) ? Wb_l : (z == 1) ? (Wb_l + 512) : Wf_l;
    int ldw = (z == 2) ? 256 : 768;
    float* out = (z == 0) ? ai : (z == 1) ? aj : nf;

    int tid = threadIdx.x;
    int lane = tid & 31, wid = tid >> 5;
    int warp_m = (wid & 1) * 32;
    int warp_n = (wid >> 1) * 32;
    int mbase = blockIdx.y * 64;
    int nbase = blockIdx.x * 64;

    float c[2][4][4];
#pragma unroll
    for (int mi = 0; mi < 2; mi++)
#pragma unroll
        for (int ni = 0; ni < 4; ni++)
#pragma unroll
            for (int q = 0; q < 4; q++) c[mi][ni][q] = 0.f;

    int lrow = tid >> 1;
    int lk0 = (tid & 1) * 16;
    const float* Aptr = A + (size_t)(mbase + lrow) * 256 + lk0;
    const float* Wptr = W + (size_t)(nbase + lrow) * ldw + lk0;
    unsigned* asw = &As[lrow * ESTRIDE + lk0];
    unsigned* bsw = &Bs[lrow * ESTRIDE + lk0];
    int lg = lane >> 2, lt = lane & 3;

    float4 ra[4], rb[4];
#pragma unroll
    for (int q = 0; q < 4; q++) {
        ra[q] = *(const float4*)(Aptr + 4 * q);
        rb[q] = *(const float4*)(Wptr + 4 * q);
    }

    for (int kt = 0; kt < 256; kt += 32) {
#pragma unroll
        for (int q = 0; q < 4; q++) {
            *(uint4*)(asw + 4 * q) = f2tf4(ra[q]);
            *(uint4*)(bsw + 4 * q) = f2tf4(rb[q]);
        }
        __syncthreads();
        if (kt + 32 < 256) {
#pragma unroll
            for (int q = 0; q < 4; q++) {
                ra[q] = *(const float4*)(Aptr + kt + 32 + 4 * q);
                rb[q] = *(const float4*)(Wptr + kt + 32 + 4 * q);
            }
        }
#pragma unroll
        for (int k8 = 0; k8 < 4; k8++) {
            int kc = k8 * 8 + lt;
            unsigned af[2][4], bf[4][2];
#pragma unroll
            for (int mi = 0; mi < 2; mi++) {
                int r0 = warp_m + mi * 16 + lg;
                af[mi][0] = As[r0 * ESTRIDE + kc];
                af[mi][1] = As[(r0 + 8) * ESTRIDE + kc];
                af[mi][2] = As[r0 * ESTRIDE + kc + 4];
                af[mi][3] = As[(r0 + 8) * ESTRIDE + kc + 4];
            }
#pragma unroll
            for (int ni = 0; ni < 4; ni++) {
                int n0 = warp_n + ni * 8 + lg;
                bf[ni][0] = Bs[n0 * ESTRIDE + kc];
                bf[ni][1] = Bs[n0 * ESTRIDE + kc + 4];
            }
#pragma unroll
            for (int mi = 0; mi < 2; mi++)
#pragma unroll
                for (int ni = 0; ni < 4; ni++)
                    mma16n8k8(c[mi][ni][0], c[mi][ni][1], c[mi][ni][2], c[mi][ni][3],
                              af[mi][0], af[mi][1], af[mi][2], af[mi][3],
                              bf[ni][0], bf[ni][1]);
        }
        __syncthreads();
    }

#pragma unroll
    for (int mi = 0; mi < 2; mi++)
#pragma unroll
        for (int half = 0; half < 2; half++) {
            int m = mbase + warp_m + mi * 16 + lg + half * 8;
#pragma unroll
            for (int ni = 0; ni < 4; ni++) {
                int col = nbase + warp_n + ni * 8 + 2 * lt;
                *(float2*)&out[(size_t)m * 256 + col] =
                    make_float2(c[mi][ni][2 * half + 0], c[mi][ni][2 * half + 1]);
            }
        }
}

// ---------------- FUSED edge layer: GEMM + epilogue + LayerNorm + dot(v) ---
// Block: 64 edge rows x 256 cols (full C). 8 warps (2m x 4n), warp tile 32x64.
// NO min-blocks bound (regs must float; the R5/R6 regressions were spills).
// out = LN( lrelu(A@Wb2^T + ai + aj)*mask + A ) ; dotv[row] = out_row . v
#define FSTR 36
__global__ void __launch_bounds__(256)
edge_fused(const float* __restrict__ A, const float* __restrict__ W,
           const float* __restrict__ ai, const float* __restrict__ aj,
           const float* __restrict__ mask,
           const float* __restrict__ lng, const float* __restrict__ lnb,
           const float* __restrict__ v,
           float* __restrict__ out, float* __restrict__ dotv)
{
    __shared__ unsigned As[64 * FSTR];    // 9216 B
    __shared__ unsigned Bs[256 * FSTR];   // 36864 B
    float* red = (float*)As;              // reused post-GEMM for reductions

    int tid = threadIdx.x;
    int lane = tid & 31, wid = tid >> 5;
    int wm = wid & 1;          // 2 m-warps
    int wn = wid >> 1;         // 4 n-warps
    int warp_m = wm * 32;
    int warp_n = wn * 64;
    int mbase = blockIdx.x * 64;
    int lg = lane >> 2, lt = lane & 3;

    float c[2][8][4];
#pragma unroll
    for (int mi = 0; mi < 2; mi++)
#pragma unroll
        for (int ni = 0; ni < 8; ni++)
#pragma unroll
            for (int q = 0; q < 4; q++) c[mi][ni][q] = 0.f;

    int arow = tid >> 2;             // 0..63 (4 threads per row)
    int ak = (tid & 3) * 8;          // 0,8,16,24
    const float* Ap = A + (size_t)(mbase + arow) * 256 + ak;
    unsigned* asw = &As[arow * FSTR + ak];

    // B: 256 rows, 4 threads/row, 4 row-passes (rr*64 + arow)
    float4 ra[2], rb[8];
#pragma unroll
    for (int q = 0; q < 2; q++) ra[q] = *(const float4*)(Ap + 4 * q);
#pragma unroll
    for (int rr = 0; rr < 4; rr++)
#pragma unroll
        for (int q = 0; q < 2; q++)
            rb[rr * 2 + q] = *(const float4*)(W + (size_t)(rr * 64 + arow) * 768 + ak + 4 * q);

    for (int kt = 0; kt < 256; kt += 32) {
#pragma unroll
        for (int q = 0; q < 2; q++)
            *(uint4*)(asw + 4 * q) = f2tf4(ra[q]);
#pragma unroll
        for (int rr = 0; rr < 4; rr++)
#pragma unroll
            for (int q = 0; q < 2; q++)
                *(uint4*)&Bs[(rr * 64 + arow) * FSTR + ak + 4 * q] = f2tf4(rb[rr * 2 + q]);
        __syncthreads();
        if (kt + 32 < 256) {
#pragma unroll
            for (int q = 0; q < 2; q++)
                ra[q] = *(const float4*)(Ap + kt + 32 + 4 * q);
#pragma unroll
            for (int rr = 0; rr < 4; rr++)
#pragma unroll
                for (int q = 0; q < 2; q++)
                    rb[rr * 2 + q] = *(const float4*)(W + (size_t)(rr * 64 + arow) * 768
                                                      + kt + 32 + ak + 4 * q);
        }
#pragma unroll
        for (int k8 = 0; k8 < 4; k8++) {
            int kc = k8 * 8 + lt;
            unsigned af[2][4], bf[8][2];
#pragma unroll
            for (int mi = 0; mi < 2; mi++) {
                int r0 = warp_m + mi * 16 + lg;
                af[mi][0] = As[r0 * FSTR + kc];
                af[mi][1] = As[(r0 + 8) * FSTR + kc];
                af[mi][2] = As[r0 * FSTR + kc + 4];
                af[mi][3] = As[(r0 + 8) * FSTR + kc + 4];
            }
#pragma unroll
            for (int ni = 0; ni < 8; ni++) {
                int n0 = warp_n + ni * 8 + lg;
                bf[ni][0] = Bs[n0 * FSTR + kc];
                bf[ni][1] = Bs[n0 * FSTR + kc + 4];
            }
#pragma unroll
            for (int mi = 0; mi < 2; mi++)
#pragma unroll
                for (int ni = 0; ni < 8; ni++)
                    mma16n8k8(c[mi][ni][0], c[mi][ni][1], c[mi][ni][2], c[mi][ni][3],
                              af[mi][0], af[mi][1], af[mi][2], af[mi][3],
                              bf[ni][0], bf[ni][1]);
        }
        __syncthreads();
    }

    // ---- epilogue phase 1: h = lrelu(acc+ai+aj)*mask + residual; row stats
#pragma unroll
    for (int mi = 0; mi < 2; mi++) {
#pragma unroll
        for (int half = 0; half < 2; half++) {
            int rloc = warp_m + mi * 16 + half * 8 + lg;    // 0..63
            int m = mbase + rloc;
            int b = m >> 14;
            int i = (m >> 7) & 127;
            int j = m & 127;
            float mv = mask[m];
            const float* aip = &ai[(size_t)((b << 7) + i) * 256];
            const float* ajp = &aj[(size_t)((b << 7) + j) * 256];
            const float* res = &A[(size_t)m * 256];
            float rs = 0.f, rq = 0.f;
#pragma unroll
            for (int ni = 0; ni < 8; ni++) {
                int col = warp_n + ni * 8 + 2 * lt;
                float2 a2 = *(const float2*)&aip[col];
                float2 j2 = *(const float2*)&ajp[col];
                float2 r2 = *(const float2*)&res[col];
                float v0 = c[mi][ni][2 * half + 0] + a2.x + j2.x;
                float v1 = c[mi][ni][2 * half + 1] + a2.y + j2.y;
                v0 = (v0 > 0.f ? v0 : ALPHA * v0) * mv + r2.x;
                v1 = (v1 > 0.f ? v1 : ALPHA * v1) * mv + r2.y;
                c[mi][ni][2 * half + 0] = v0;
                c[mi][ni][2 * half + 1] = v1;
                rs += v0 + v1;
                rq += v0 * v0 + v1 * v1;
            }
            rs += __shfl_xor_sync(0xffffffffu, rs, 1);
            rs += __shfl_xor_sync(0xffffffffu, rs, 2);
            rq += __shfl_xor_sync(0xffffffffu, rq, 1);
            rq += __shfl_xor_sync(0xffffffffu, rq, 2);
            if (lt == 0) {
                red[wn * 64 + rloc] = rs;
                red[256 + wn * 64 + rloc] = rq;
            }
        }
    }
    __syncthreads();
    if (tid < 64) {
        float S = red[tid] + red[64 + tid] + red[128 + tid] + red[192 + tid];
        float Q = red[256 + tid] + red[320 + tid] + red[384 + tid] + red[448 + tid];
        float mean = S * (1.f / 256.f);
        float var = Q * (1.f / 256.f) - mean * mean;
        red[512 + tid] = mean;
        red[576 + tid] = rsqrtf(var + LN_EPS);
    }
    __syncthreads();

    // ---- epilogue phase 2: normalize, store, dot with v
#pragma unroll
    for (int mi = 0; mi < 2; mi++) {
#pragma unroll
        for (int half = 0; half < 2; half++) {
            int rloc = warp_m + mi * 16 + half * 8 + lg;
            int m = mbase + rloc;
            float mean = red[512 + rloc];
            float inv = red[576 + rloc];
            float dvp = 0.f;
#pragma unroll
            for (int ni = 0; ni < 8; ni++) {
                int col = warp_n + ni * 8 + 2 * lt;
                float2 g2 = *(const float2*)&lng[col];
                float2 b2 = *(const float2*)&lnb[col];
                float2 v2 = *(const float2*)&v[col];
                float y0 = (c[mi][ni][2 * half + 0] - mean) * inv * g2.x + b2.x;
                float y1 = (c[mi][ni][2 * half + 1] - mean) * inv * g2.y + b2.y;
                *(float2*)&out[(size_t)m * 256 + col] = make_float2(y0, y1);
                dvp += y0 * v2.x + y1 * v2.y;
            }
            dvp += __shfl_xor_sync(0xffffffffu, dvp, 1);
            dvp += __shfl_xor_sync(0xffffffffu, dvp, 2);
            if (lt == 0) red[wn * 64 + rloc] = dvp;   // stats region 512+ untouched
        }
    }
    __syncthreads();
    if (tid < 64)
        dotv[mbase + tid] = red[tid] + red[64 + tid] + red[128 + tid] + red[192 + tid];
}

// ---------------- v = Wbp^T ub, w = Wfp^T ub, s = nodes·w (merged) ---------
__global__ void vws_kernel(const float* __restrict__ Wbp, const float* __restrict__ Wfp,
                           const float* __restrict__ ub, const float* __restrict__ nodes,
                           float* __restrict__ v, float* __restrict__ w,
                           float* __restrict__ s)
{
    __shared__ float ws[256];
    int k = threadIdx.x;
    float a = 0.f, b = 0.f;
    for (int c = 0; c < 256; c++) {
        float u = ub[c];
        a += u * Wbp[c * 256 + k];
        b += u * Wfp[c * 256 + k];
    }
    v[k] = a; w[k] = b;
    ws[k] = b;
    __syncthreads();
    float acc = 0.f;
    const float* rp = nodes + (size_t)k * 256;
    for (int c = 0; c < 256; c++) acc += rp[c] * ws[c];
    s[k] = acc;
}

// ---------------- attention + node update (LN fused) -----------------------
__global__ void __launch_bounds__(256)
attn_kernel(const float* __restrict__ dotv, const float* __restrict__ s,
            const float* __restrict__ nf, const float* __restrict__ mask,
            const float* __restrict__ nodes_old, const float* __restrict__ g,
            const float* __restrict__ bt, float* __restrict__ nodes_new)
{
    int bi = blockIdx.x;
    int b = bi >> 7, i = bi & 127;
    int t = threadIdx.x;
    __shared__ float sm_a[128];
    __shared__ float sred1[8], sred2[8];
    __shared__ float sm_m, sm_sum, sm_mean, sm_inv;

    if (t < 128) {
        int j = t;
        float mv = mask[b * 16384 + i * 128 + j];
        float r;
        if (mv > 0.f) {
            float dv = dotv[b * 16384 + j * 128 + i];
            r = dv + s[b * 128 + i] + s[b * 128 + j];
            r = r > 0.f ? r : ALPHA * r;
        } else {
            r = NEG_BIG;
        }
        sm_a[j] = r;
    }
    __syncthreads();
    if (t < 32) {
        float m = fmaxf(fmaxf(sm_a[t], sm_a[t + 32]), fmaxf(sm_a[t + 64], sm_a[t + 96]));
#pragma unroll
        for (int o = 16; o; o >>= 1) m = fmaxf(m, __shfl_xor_sync(0xffffffffu, m, o));
        if (t == 0) sm_m = m;
    }
    __syncthreads();
    if (t < 128) sm_a[t] = expf(sm_a[t] - sm_m);
    __syncthreads();
    if (t < 32) {
        float su = sm_a[t] + sm_a[t + 32] + sm_a[t + 64] + sm_a[t + 96];
#pragma unroll
        for (int o = 16; o; o >>= 1) su += __shfl_xor_sync(0xffffffffu, su, o);
        if (t == 0) sm_sum = su;
    }
    __syncthreads();
    float inv_sum = 1.f / sm_sum;

    int c = t;
    float acc = 0.f;
    const float* nfb = nf + (size_t)b * Nn * Cc + c;
#pragma unroll 4
    for (int j = 0; j < 128; j++) acc += sm_a[j] * nfb[(size_t)j * Cc];
    acc *= inv_sum;
    float h = (acc > 0.f ? acc : ALPHA * acc) + nodes_old[(size_t)(b * 128 + i) * 256 + c];

    int lane = t & 31, wp = t >> 5;
    float su = h, sq = h * h;
#pragma unroll
    for (int o = 16; o; o >>= 1) {
        su += __shfl_xor_sync(0xffffffffu, su, o);
        sq += __shfl_xor_sync(0xffffffffu, sq, o);
    }
    if (lane == 0) { sred1[wp] = su; sred2[wp] = sq; }
    __syncthreads();
    if (t == 0) {
        float S = 0.f, Q = 0.f;
#pragma unroll
        for (int w2 = 0; w2 < 8; w2++) { S += sred1[w2]; Q += sred2[w2]; }
        float mean = S * (1.f / 256.f);
        float var = Q * (1.f / 256.f) - mean * mean;
        sm_mean = mean;
        sm_inv = rsqrtf(var + LN_EPS);
    }
    __syncthreads();
    nodes_new[(size_t)(b * 128 + i) * 256 + c] = (h - sm_mean) * sm_inv * g[c] + bt[c];
}

// ---------------- edge logits: out[row,k] = e[row]·ecW[k] + ecb[k] ---------
__global__ void edge_logits_kernel(const float* __restrict__ e, const float* __restrict__ W,
                                   const float* __restrict__ bias, float* __restrict__ out)
{
    int warp = threadIdx.x >> 5, lane = threadIdx.x & 31;
    int row = blockIdx.x * 8 + warp;
    const float* rp = e + (size_t)row * 256;
    float x[8];
#pragma unroll
    for (int q = 0; q < 8; q++) x[q] = rp[lane + q * 32];
#pragma unroll
    for (int k = 0; k < KE_; k++) {
        float acc = 0.f;
#pragma unroll
        for (int q = 0; q < 8; q++) acc += x[q] * W[k * 256 + lane + q * 32];
#pragma unroll
        for (int o = 16; o; o >>= 1) acc += __shfl_xor_sync(0xffffffffu, acc, o);
        if (lane == 0) out[(size_t)row * KE_ + k] = acc + bias[k];
    }
}

// ---------------- host ------------------------------------------------------
extern "C" void kernel_launch(void* const* d_in, const int* in_sizes, int n_in,
                              void* d_out, int out_size)
{
    const float* nodes_in = (const float*)d_in[0];
    const float* edges_in = (const float*)d_in[1];
    const float* adj      = (const float*)d_in[2];
    const float* pnW = (const float*)d_in[3];
    const float* pnb = (const float*)d_in[4];
    const float* peW = (const float*)d_in[5];
    const float* peb = (const float*)d_in[6];
    const float* Wb  = (const float*)d_in[7];
    const float* Wbp = (const float*)d_in[8];
    const float* Wfp = (const float*)d_in[9];
    const float* ub  = (const float*)d_in[10];
    const float* Wf  = (const float*)d_in[11];
    const float* eln_g = (const float*)d_in[12];
    const float* eln_b = (const float*)d_in[13];
    const float* nln_g = (const float*)d_in[14];
    const float* nln_b = (const float*)d_in[15];
    const float* ncW = (const float*)d_in[16];
    const float* ncb = (const float*)d_in[17];
    const float* ecW = (const float*)d_in[18];
    const float* ecb = (const float*)d_in[19];

    float *eA, *eB, *n0, *n1, *ai_, *aj_, *nf_, *s_, *v_, *w_, *dv_;
    cudaGetSymbolAddress((void**)&eA, g_eA);
    cudaGetSymbolAddress((void**)&eB, g_eB);
    cudaGetSymbolAddress((void**)&n0, g_n0);
    cudaGetSymbolAddress((void**)&n1, g_n1);
    cudaGetSymbolAddress((void**)&ai_, g_ai);
    cudaGetSymbolAddress((void**)&aj_, g_aj);
    cudaGetSymbolAddress((void**)&nf_, g_nf);
    cudaGetSymbolAddress((void**)&s_, g_s);
    cudaGetSymbolAddress((void**)&v_, g_v);
    cudaGetSymbolAddress((void**)&w_, g_w);
    cudaGetSymbolAddress((void**)&dv_, g_dotv);

    float* out = (float*)d_out;
    float* out_nodes = out;
    float* out_edges = out + NODES_SZ;

    // ping-pong schedule; layer 2 writes land directly in d_out (no copies)
    float* ebuf[4] = {eA, eB, eA, out_edges};
    float* nbuf[4] = {n0, n1, n0, out_nodes};

    dim3 bs(16, 16);

    // initial projections
    gemm_small<<<dim3(16, 16), bs>>>(nodes_in, pnW, pnb, nbuf[0], 256, 256, 128, 128);
    edge_proj_mma<<<dim3(2, 256), 256>>>(edges_in, peW, 64, 64, peb, ebuf[0]);

    for (int l = 0; l < 3; l++) {
        const float* Wb_l  = Wb  + (size_t)l * 256 * 768;
        const float* Wbp_l = Wbp + (size_t)l * 65536;
        const float* Wfp_l = Wfp + (size_t)l * 65536;
        const float* ub_l  = ub  + l * 256;
        const float* Wf_l  = Wf  + (size_t)l * 65536;
        float* ecur = ebuf[l]; float* enxt = ebuf[l + 1];
        float* ncur = nbuf[l]; float* nnxt = nbuf[l + 1];

        vws_kernel<<<1, 256>>>(Wbp_l, Wfp_l, ub_l, ncur, v_, w_, s_);
        node3_mma<<<dim3(4, 4, 3), 128>>>(ncur, Wb_l, Wf_l, ai_, aj_, nf_);

        edge_fused<<<512, 256>>>(ecur, Wb_l + 256, ai_, aj_, adj,
                                 eln_g + l * 256, eln_b + l * 256, v_,
                                 enxt, dv_);
        attn_kernel<<<256, 256>>>(dv_, s_, nf_, adj, ncur,
                                  nln_g + l * 256, nln_b + l * 256, nnxt);
    }

    // final heads read directly from d_out regions
    gemm_small<<<dim3(7, 16), bs>>>(nbuf[3], ncW, ncb, out + NODES_SZ + EDGES_SZ,
                                    256, KN_, 256, 256);
    edge_logits_kernel<<<4096, 256>>>(ebuf[3], ecW, ecb,
                                      out + NODES_SZ + EDGES_SZ + 256 * KN_);
}

// round 10
// speedup vs baseline: 1.4606x; 1.0113x over previous
#include <cuda_runtime.h>

#define Bb 2
#define Nn 128
#define Cc 256
#define BN2 (Bb*Nn*Nn)        // 32768 edge rows
#define NODES_SZ (Bb*Nn*Cc)   // 65536
#define EDGES_SZ (BN2*Cc)     // 8388608
#define KN_ 101
#define KE_ 7
#define ALPHA 0.2f
#define LN_EPS 1e-5f
#define NEG_BIG (-1e30f)

// ---------------- scratch (device globals: allocation-free) ----------------
__device__ float g_eA[EDGES_SZ];
__device__ float g_eB[EDGES_SZ];
__device__ float g_n0[NODES_SZ];
__device__ float g_n1[NODES_SZ];
__device__ float g_ai[NODES_SZ];
__device__ float g_aj[NODES_SZ];
__device__ float g_nf[NODES_SZ];
__device__ float g_s[Bb*Nn];
__device__ float g_v[Cc];
__device__ float g_w[Cc];
__device__ float g_dotv[BN2];

// ---------------- tf32 helpers ---------------------------------------------
__device__ __forceinline__ unsigned f2tf(float f)
{
    unsigned r;
    asm("cvt.rna.tf32.f32 %0, %1;" : "=r"(r) : "f"(f));
    return r;
}
__device__ __forceinline__ uint4 f2tf4(float4 v)
{
    return make_uint4(f2tf(v.x), f2tf(v.y), f2tf(v.z), f2tf(v.w));
}
__device__ __forceinline__ void mma16n8k8(float& c0, float& c1, float& c2, float& c3,
                                          unsigned a0, unsigned a1, unsigned a2, unsigned a3,
                                          unsigned b0, unsigned b1)
{
    asm volatile("mma.sync.aligned.m16n8k8.row.col.f32.tf32.tf32.f32 "
                 "{%0,%1,%2,%3}, {%4,%5,%6,%7}, {%8,%9}, {%0,%1,%2,%3};"
                 : "+f"(c0), "+f"(c1), "+f"(c2), "+f"(c3)
                 : "r"(a0), "r"(a1), "r"(a2), "r"(a3), "r"(b0), "r"(b1));
}

// ---------------- small generic GEMM: out[m,n] = A[m,:]·W[n,:] + bias ------
__global__ void gemm_small(const float* __restrict__ A, const float* __restrict__ W,
                           const float* __restrict__ bias, float* __restrict__ out,
                           int M, int N, int K, int ldw)
{
    __shared__ float As[16][16];
    __shared__ float Ws[16][17];
    int tx = threadIdx.x, ty = threadIdx.y;
    int m = blockIdx.y * 16 + ty;
    int n = blockIdx.x * 16 + tx;
    float acc = 0.f;
    for (int k0 = 0; k0 < K; k0 += 16) {
        As[ty][tx] = (m < M) ? A[m * K + k0 + tx] : 0.f;
        int nn = blockIdx.x * 16 + ty;
        Ws[ty][tx] = (nn < N) ? W[(size_t)nn * ldw + k0 + tx] : 0.f;
        __syncthreads();
#pragma unroll
        for (int kk = 0; kk < 16; kk++) acc += As[ty][kk] * Ws[tx][kk];
        __syncthreads();
    }
    if (m < M && n < N) {
        float b = bias ? bias[n] : 0.f;
        out[m * N + n] = acc + b;
    }
}

// ---------------- edge projection GEMM (K=64): 512 thr, 128x128 tile -------
// 16 warps as 4m x 4n, warp tile 32x32 -> 32 acc regs/thread, ~95 regs total
#define ESTRIDE 36
__global__ void __launch_bounds__(512)
edge_proj_mma(const float* __restrict__ A, const float* __restrict__ W,
              int K, int ldw, const float* __restrict__ bias, float* __restrict__ out)
{
    __shared__ unsigned As[128 * ESTRIDE];
    __shared__ unsigned Bs[128 * ESTRIDE];
    int tid = threadIdx.x;
    int lane = tid & 31, wid = tid >> 5;
    int warp_m = (wid & 3) * 32;
    int warp_n = (wid >> 2) * 32;
    int mbase = blockIdx.y * 128;
    int nbase = blockIdx.x * 128;
    int lg = lane >> 2, lt = lane & 3;

    float c[2][4][4];
#pragma unroll
    for (int mi = 0; mi < 2; mi++)
#pragma unroll
        for (int ni = 0; ni < 4; ni++)
#pragma unroll
            for (int q = 0; q < 4; q++) c[mi][ni][q] = 0.f;

    int lrow = tid >> 2;             // 0..127
    int lk0 = (tid & 3) * 8;         // 0,8,16,24
    const float* Aptr = A + (size_t)(mbase + lrow) * K + lk0;
    const float* Wptr = W + (size_t)(nbase + lrow) * ldw + lk0;
    unsigned* asw = &As[lrow * ESTRIDE + lk0];
    unsigned* bsw = &Bs[lrow * ESTRIDE + lk0];

    float4 ra[2], rb[2];
#pragma unroll
    for (int q = 0; q < 2; q++) {
        ra[q] = *(const float4*)(Aptr + 4 * q);
        rb[q] = *(const float4*)(Wptr + 4 * q);
    }

    for (int kt = 0; kt < K; kt += 32) {
#pragma unroll
        for (int q = 0; q < 2; q++) {
            *(uint4*)(asw + 4 * q) = f2tf4(ra[q]);
            *(uint4*)(bsw + 4 * q) = f2tf4(rb[q]);
        }
        __syncthreads();
        if (kt + 32 < K) {
#pragma unroll
            for (int q = 0; q < 2; q++) {
                ra[q] = *(const float4*)(Aptr + kt + 32 + 4 * q);
                rb[q] = *(const float4*)(Wptr + kt + 32 + 4 * q);
            }
        }
#pragma unroll
        for (int k8 = 0; k8 < 4; k8++) {
            int kc = k8 * 8 + lt;
            unsigned af[2][4], bf[4][2];
#pragma unroll
            for (int mi = 0; mi < 2; mi++) {
                int r0 = warp_m + mi * 16 + lg;
                af[mi][0] = As[r0 * ESTRIDE + kc];
                af[mi][1] = As[(r0 + 8) * ESTRIDE + kc];
                af[mi][2] = As[r0 * ESTRIDE + kc + 4];
                af[mi][3] = As[(r0 + 8) * ESTRIDE + kc + 4];
            }
#pragma unroll
            for (int ni = 0; ni < 4; ni++) {
                int n0 = warp_n + ni * 8 + lg;
                bf[ni][0] = Bs[n0 * ESTRIDE + kc];
                bf[ni][1] = Bs[n0 * ESTRIDE + kc + 4];
            }
#pragma unroll
            for (int mi = 0; mi < 2; mi++)
#pragma unroll
                for (int ni = 0; ni < 4; ni++)
                    mma16n8k8(c[mi][ni][0], c[mi][ni][1], c[mi][ni][2], c[mi][ni][3],
                              af[mi][0], af[mi][1], af[mi][2], af[mi][3],
                              bf[ni][0], bf[ni][1]);
        }
        __syncthreads();
    }

#pragma unroll
    for (int mi = 0; mi < 2; mi++)
#pragma unroll
        for (int half = 0; half < 2; half++) {
            int m = mbase + warp_m + mi * 16 + lg + half * 8;
#pragma unroll
            for (int ni = 0; ni < 4; ni++) {
                int col = nbase + warp_n + ni * 8 + 2 * lt;
                float2 bv = *(const float2*)&bias[col];
                *(float2*)&out[(size_t)m * 256 + col] =
                    make_float2(c[mi][ni][2 * half + 0] + bv.x,
                                c[mi][ni][2 * half + 1] + bv.y);
            }
        }
}

// ---------------- node GEMMs: 64x64 tiles, 48 blocks, pipelined ------------
__global__ void __launch_bounds__(128)
node3_mma(const float* __restrict__ A, const float* __restrict__ Wb_l,
          const float* __restrict__ Wf_l,
          float* __restrict__ ai, float* __restrict__ aj, float* __restrict__ nf)
{
    __shared__ unsigned As[64 * ESTRIDE];
    __shared__ unsigned Bs[64 * ESTRIDE];
    int z = blockIdx.z;
    const float* W = (z == 0) ? Wb_l : (z == 1) ? (Wb_l + 512) : Wf_l;
    int ldw = (z == 2) ? 256 : 768;
    float* out = (z == 0) ? ai : (z == 1) ? aj : nf;

    int tid = threadIdx.x;
    int lane = tid & 31, wid = tid >> 5;
    int warp_m = (wid & 1) * 32;
    int warp_n = (wid >> 1) * 32;
    int mbase = blockIdx.y * 64;
    int nbase = blockIdx.x * 64;

    float c[2][4][4];
#pragma unroll
    for (int mi = 0; mi < 2; mi++)
#pragma unroll
        for (int ni = 0; ni < 4; ni++)
#pragma unroll
            for (int q = 0; q < 4; q++) c[mi][ni][q] = 0.f;

    int lrow = tid >> 1;
    int lk0 = (tid & 1) * 16;
    const float* Aptr = A + (size_t)(mbase + lrow) * 256 + lk0;
    const float* Wptr = W + (size_t)(nbase + lrow) * ldw + lk0;
    unsigned* asw = &As[lrow * ESTRIDE + lk0];
    unsigned* bsw = &Bs[lrow * ESTRIDE + lk0];
    int lg = lane >> 2, lt = lane & 3;

    float4 ra[4], rb[4];
#pragma unroll
    for (int q = 0; q < 4; q++) {
        ra[q] = *(const float4*)(Aptr + 4 * q);
        rb[q] = *(const float4*)(Wptr + 4 * q);
    }

    for (int kt = 0; kt < 256; kt += 32) {
#pragma unroll
        for (int q = 0; q < 4; q++) {
            *(uint4*)(asw + 4 * q) = f2tf4(ra[q]);
            *(uint4*)(bsw + 4 * q) = f2tf4(rb[q]);
        }
        __syncthreads();
        if (kt + 32 < 256) {
#pragma unroll
            for (int q = 0; q < 4; q++) {
                ra[q] = *(const float4*)(Aptr + kt + 32 + 4 * q);
                rb[q] = *(const float4*)(Wptr + kt + 32 + 4 * q);
            }
        }
#pragma unroll
        for (int k8 = 0; k8 < 4; k8++) {
            int kc = k8 * 8 + lt;
            unsigned af[2][4], bf[4][2];
#pragma unroll
            for (int mi = 0; mi < 2; mi++) {
                int r0 = warp_m + mi * 16 + lg;
                af[mi][0] = As[r0 * ESTRIDE + kc];
                af[mi][1] = As[(r0 + 8) * ESTRIDE + kc];
                af[mi][2] = As[r0 * ESTRIDE + kc + 4];
                af[mi][3] = As[(r0 + 8) * ESTRIDE + kc + 4];
            }
#pragma unroll
            for (int ni = 0; ni < 4; ni++) {
                int n0 = warp_n + ni * 8 + lg;
                bf[ni][0] = Bs[n0 * ESTRIDE + kc];
                bf[ni][1] = Bs[n0 * ESTRIDE + kc + 4];
            }
#pragma unroll
            for (int mi = 0; mi < 2; mi++)
#pragma unroll
                for (int ni = 0; ni < 4; ni++)
                    mma16n8k8(c[mi][ni][0], c[mi][ni][1], c[mi][ni][2], c[mi][ni][3],
                              af[mi][0], af[mi][1], af[mi][2], af[mi][3],
                              bf[ni][0], bf[ni][1]);
        }
        __syncthreads();
    }

#pragma unroll
    for (int mi = 0; mi < 2; mi++)
#pragma unroll
        for (int half = 0; half < 2; half++) {
            int m = mbase + warp_m + mi * 16 + lg + half * 8;
#pragma unroll
            for (int ni = 0; ni < 4; ni++) {
                int col = nbase + warp_n + ni * 8 + 2 * lt;
                *(float2*)&out[(size_t)m * 256 + col] =
                    make_float2(c[mi][ni][2 * half + 0], c[mi][ni][2 * half + 1]);
            }
        }
}

// ---------------- FUSED edge layer, 512 threads ----------------------------
// Tile 64 rows x 256 cols. 16 warps as 2m x 8n, warp tile 32x32.
// ~95 regs/thread -> 1 CTA of 16 warps/SM (2x the warps of the 256-thr ver).
// out = LN( lrelu(A@Wb2^T + ai + aj)*mask + A ) ; dotv[row] = out_row . v
#define FSTR 36
__global__ void __launch_bounds__(512)
edge_fused(const float* __restrict__ A, const float* __restrict__ W,
           const float* __restrict__ ai, const float* __restrict__ aj,
           const float* __restrict__ mask,
           const float* __restrict__ lng, const float* __restrict__ lnb,
           const float* __restrict__ v,
           float* __restrict__ out, float* __restrict__ dotv)
{
    __shared__ unsigned As[64 * FSTR];    // 9216 B (also reduction scratch)
    __shared__ unsigned Bs[256 * FSTR];   // 36864 B
    float* red = (float*)As;

    int tid = threadIdx.x;
    int lane = tid & 31, wid = tid >> 5;
    int wm = wid & 1;          // 2 m-warps (32 rows each)
    int wn = wid >> 1;         // 8 n-warps (32 cols each)
    int warp_m = wm * 32;
    int warp_n = wn * 32;
    int mbase = blockIdx.x * 64;
    int lg = lane >> 2, lt = lane & 3;

    float c[2][4][4];
#pragma unroll
    for (int mi = 0; mi < 2; mi++)
#pragma unroll
        for (int ni = 0; ni < 4; ni++)
#pragma unroll
            for (int q = 0; q < 4; q++) c[mi][ni][q] = 0.f;

    // loaders: 512 threads; A: 64x32 (1 float4/thr); B: 256x32 (4 float4/thr)
    int arow = tid >> 3;             // 0..63
    int ak = (tid & 7) * 4;          // 0,4,...,28
    const float* Ap = A + (size_t)(mbase + arow) * 256 + ak;
    unsigned* asw = &As[arow * FSTR + ak];
    const float* Wp = W + (size_t)arow * 768 + ak;

    float4 ra, rb[4];
    ra = *(const float4*)Ap;
#pragma unroll
    for (int rr = 0; rr < 4; rr++)
        rb[rr] = *(const float4*)(Wp + (size_t)rr * 64 * 768);

    for (int kt = 0; kt < 256; kt += 32) {
        *(uint4*)asw = f2tf4(ra);
#pragma unroll
        for (int rr = 0; rr < 4; rr++)
            *(uint4*)&Bs[(rr * 64 + arow) * FSTR + ak] = f2tf4(rb[rr]);
        __syncthreads();
        if (kt + 32 < 256) {
            ra = *(const float4*)(Ap + kt + 32);
#pragma unroll
            for (int rr = 0; rr < 4; rr++)
                rb[rr] = *(const float4*)(Wp + (size_t)rr * 64 * 768 + kt + 32);
        }
#pragma unroll
        for (int k8 = 0; k8 < 4; k8++) {
            int kc = k8 * 8 + lt;
            unsigned af[2][4], bf[4][2];
#pragma unroll
            for (int mi = 0; mi < 2; mi++) {
                int r0 = warp_m + mi * 16 + lg;
                af[mi][0] = As[r0 * FSTR + kc];
                af[mi][1] = As[(r0 + 8) * FSTR + kc];
                af[mi][2] = As[r0 * FSTR + kc + 4];
                af[mi][3] = As[(r0 + 8) * FSTR + kc + 4];
            }
#pragma unroll
            for (int ni = 0; ni < 4; ni++) {
                int n0 = warp_n + ni * 8 + lg;
                bf[ni][0] = Bs[n0 * FSTR + kc];
                bf[ni][1] = Bs[n0 * FSTR + kc + 4];
            }
#pragma unroll
            for (int mi = 0; mi < 2; mi++)
#pragma unroll
                for (int ni = 0; ni < 4; ni++)
                    mma16n8k8(c[mi][ni][0], c[mi][ni][1], c[mi][ni][2], c[mi][ni][3],
                              af[mi][0], af[mi][1], af[mi][2], af[mi][3],
                              bf[ni][0], bf[ni][1]);
        }
        __syncthreads();
    }

    // ---- epilogue phase 1: h = lrelu(acc+ai+aj)*mask + residual; row stats
    // red layout: rs [0,512), rq [512,1024), mean [1024,1088), inv [1088,1152)
#pragma unroll
    for (int mi = 0; mi < 2; mi++) {
#pragma unroll
        for (int half = 0; half < 2; half++) {
            int rloc = warp_m + mi * 16 + half * 8 + lg;    // 0..63
            int m = mbase + rloc;
            int b = m >> 14;
            int i = (m >> 7) & 127;
            int j = m & 127;
            float mv = mask[m];
            const float* aip = &ai[(size_t)((b << 7) + i) * 256];
            const float* ajp = &aj[(size_t)((b << 7) + j) * 256];
            const float* res = &A[(size_t)m * 256];
            float rs = 0.f, rq = 0.f;
#pragma unroll
            for (int ni = 0; ni < 4; ni++) {
                int col = warp_n + ni * 8 + 2 * lt;
                float2 a2 = *(const float2*)&aip[col];
                float2 j2 = *(const float2*)&ajp[col];
                float2 r2 = *(const float2*)&res[col];
                float v0 = c[mi][ni][2 * half + 0] + a2.x + j2.x;
                float v1 = c[mi][ni][2 * half + 1] + a2.y + j2.y;
                v0 = (v0 > 0.f ? v0 : ALPHA * v0) * mv + r2.x;
                v1 = (v1 > 0.f ? v1 : ALPHA * v1) * mv + r2.y;
                c[mi][ni][2 * half + 0] = v0;
                c[mi][ni][2 * half + 1] = v1;
                rs += v0 + v1;
                rq += v0 * v0 + v1 * v1;
            }
            rs += __shfl_xor_sync(0xffffffffu, rs, 1);
            rs += __shfl_xor_sync(0xffffffffu, rs, 2);
            rq += __shfl_xor_sync(0xffffffffu, rq, 1);
            rq += __shfl_xor_sync(0xffffffffu, rq, 2);
            if (lt == 0) {
                red[wn * 64 + rloc] = rs;
                red[512 + wn * 64 + rloc] = rq;
            }
        }
    }
    __syncthreads();
    if (tid < 64) {
        float S = 0.f, Q = 0.f;
#pragma unroll
        for (int w8 = 0; w8 < 8; w8++) {
            S += red[w8 * 64 + tid];
            Q += red[512 + w8 * 64 + tid];
        }
        float mean = S * (1.f / 256.f);
        float var = Q * (1.f / 256.f) - mean * mean;
        red[1024 + tid] = mean;
        red[1088 + tid] = rsqrtf(var + LN_EPS);
    }
    __syncthreads();

    // ---- epilogue phase 2: normalize, store, dot with v
#pragma unroll
    for (int mi = 0; mi < 2; mi++) {
#pragma unroll
        for (int half = 0; half < 2; half++) {
            int rloc = warp_m + mi * 16 + half * 8 + lg;
            int m = mbase + rloc;
            float mean = red[1024 + rloc];
            float inv = red[1088 + rloc];
            float dvp = 0.f;
#pragma unroll
            for (int ni = 0; ni < 4; ni++) {
                int col = warp_n + ni * 8 + 2 * lt;
                float2 g2 = *(const float2*)&lng[col];
                float2 b2 = *(const float2*)&lnb[col];
                float2 v2 = *(const float2*)&v[col];
                float y0 = (c[mi][ni][2 * half + 0] - mean) * inv * g2.x + b2.x;
                float y1 = (c[mi][ni][2 * half + 1] - mean) * inv * g2.y + b2.y;
                *(float2*)&out[(size_t)m * 256 + col] = make_float2(y0, y1);
                dvp += y0 * v2.x + y1 * v2.y;
            }
            dvp += __shfl_xor_sync(0xffffffffu, dvp, 1);
            dvp += __shfl_xor_sync(0xffffffffu, dvp, 2);
            if (lt == 0) red[wn * 64 + rloc] = dvp;   // stats at 1024+ untouched
        }
    }
    __syncthreads();
    if (tid < 64) {
        float S = 0.f;
#pragma unroll
        for (int w8 = 0; w8 < 8; w8++) S += red[w8 * 64 + tid];
        dotv[mbase + tid] = S;
    }
}

// ---------------- v = Wbp^T ub, w = Wfp^T ub, s = nodes·w (merged) ---------
__global__ void vws_kernel(const float* __restrict__ Wbp, const float* __restrict__ Wfp,
                           const float* __restrict__ ub, const float* __restrict__ nodes,
                           float* __restrict__ v, float* __restrict__ w,
                           float* __restrict__ s)
{
    __shared__ float ws[256];
    int k = threadIdx.x;
    float a = 0.f, b = 0.f;
    for (int c = 0; c < 256; c++) {
        float u = ub[c];
        a += u * Wbp[c * 256 + k];
        b += u * Wfp[c * 256 + k];
    }
    v[k] = a; w[k] = b;
    ws[k] = b;
    __syncthreads();
    float acc = 0.f;
    const float* rp = nodes + (size_t)k * 256;
    for (int c = 0; c < 256; c++) acc += rp[c] * ws[c];
    s[k] = acc;
}

// ---------------- attention + node update (LN fused) -----------------------
__global__ void __launch_bounds__(256)
attn_kernel(const float* __restrict__ dotv, const float* __restrict__ s,
            const float* __restrict__ nf, const float* __restrict__ mask,
            const float* __restrict__ nodes_old, const float* __restrict__ g,
            const float* __restrict__ bt, float* __restrict__ nodes_new)
{
    int bi = blockIdx.x;
    int b = bi >> 7, i = bi & 127;
    int t = threadIdx.x;
    __shared__ float sm_a[128];
    __shared__ float sred1[8], sred2[8];
    __shared__ float sm_m, sm_sum, sm_mean, sm_inv;

    if (t < 128) {
        int j = t;
        float mv = mask[b * 16384 + i * 128 + j];
        float r;
        if (mv > 0.f) {
            float dv = dotv[b * 16384 + j * 128 + i];
            r = dv + s[b * 128 + i] + s[b * 128 + j];
            r = r > 0.f ? r : ALPHA * r;
        } else {
            r = NEG_BIG;
        }
        sm_a[j] = r;
    }
    __syncthreads();
    if (t < 32) {
        float m = fmaxf(fmaxf(sm_a[t], sm_a[t + 32]), fmaxf(sm_a[t + 64], sm_a[t + 96]));
#pragma unroll
        for (int o = 16; o; o >>= 1) m = fmaxf(m, __shfl_xor_sync(0xffffffffu, m, o));
        if (t == 0) sm_m = m;
    }
    __syncthreads();
    if (t < 128) sm_a[t] = expf(sm_a[t] - sm_m);
    __syncthreads();
    if (t < 32) {
        float su = sm_a[t] + sm_a[t + 32] + sm_a[t + 64] + sm_a[t + 96];
#pragma unroll
        for (int o = 16; o; o >>= 1) su += __shfl_xor_sync(0xffffffffu, su, o);
        if (t == 0) sm_sum = su;
    }
    __syncthreads();
    float inv_sum = 1.f / sm_sum;

    int c = t;
    float acc = 0.f;
    const float* nfb = nf + (size_t)b * Nn * Cc + c;
#pragma unroll 4
    for (int j = 0; j < 128; j++) acc += sm_a[j] * nfb[(size_t)j * Cc];
    acc *= inv_sum;
    float h = (acc > 0.f ? acc : ALPHA * acc) + nodes_old[(size_t)(b * 128 + i) * 256 + c];

    int lane = t & 31, wp = t >> 5;
    float su = h, sq = h * h;
#pragma unroll
    for (int o = 16; o; o >>= 1) {
        su += __shfl_xor_sync(0xffffffffu, su, o);
        sq += __shfl_xor_sync(0xffffffffu, sq, o);
    }
    if (lane == 0) { sred1[wp] = su; sred2[wp] = sq; }
    __syncthreads();
    if (t == 0) {
        float S = 0.f, Q = 0.f;
#pragma unroll
        for (int w2 = 0; w2 < 8; w2++) { S += sred1[w2]; Q += sred2[w2]; }
        float mean = S * (1.f / 256.f);
        float var = Q * (1.f / 256.f) - mean * mean;
        sm_mean = mean;
        sm_inv = rsqrtf(var + LN_EPS);
    }
    __syncthreads();
    nodes_new[(size_t)(b * 128 + i) * 256 + c] = (h - sm_mean) * sm_inv * g[c] + bt[c];
}

// ---------------- edge logits: out[row,k] = e[row]·ecW[k] + ecb[k] ---------
__global__ void edge_logits_kernel(const float* __restrict__ e, const float* __restrict__ W,
                                   const float* __restrict__ bias, float* __restrict__ out)
{
    int warp = threadIdx.x >> 5, lane = threadIdx.x & 31;
    int row = blockIdx.x * 8 + warp;
    const float* rp = e + (size_t)row * 256;
    float x[8];
#pragma unroll
    for (int q = 0; q < 8; q++) x[q] = rp[lane + q * 32];
#pragma unroll
    for (int k = 0; k < KE_; k++) {
        float acc = 0.f;
#pragma unroll
        for (int q = 0; q < 8; q++) acc += x[q] * W[k * 256 + lane + q * 32];
#pragma unroll
        for (int o = 16; o; o >>= 1) acc += __shfl_xor_sync(0xffffffffu, acc, o);
        if (lane == 0) out[(size_t)row * KE_ + k] = acc + bias[k];
    }
}

// ---------------- host ------------------------------------------------------
extern "C" void kernel_launch(void* const* d_in, const int* in_sizes, int n_in,
                              void* d_out, int out_size)
{
    const float* nodes_in = (const float*)d_in[0];
    const float* edges_in = (const float*)d_in[1];
    const float* adj      = (const float*)d_in[2];
    const float* pnW = (const float*)d_in[3];
    const float* pnb = (const float*)d_in[4];
    const float* peW = (const float*)d_in[5];
    const float* peb = (const float*)d_in[6];
    const float* Wb  = (const float*)d_in[7];
    const float* Wbp = (const float*)d_in[8];
    const float* Wfp = (const float*)d_in[9];
    const float* ub  = (const float*)d_in[10];
    const float* Wf  = (const float*)d_in[11];
    const float* eln_g = (const float*)d_in[12];
    const float* eln_b = (const float*)d_in[13];
    const float* nln_g = (const float*)d_in[14];
    const float* nln_b = (const float*)d_in[15];
    const float* ncW = (const float*)d_in[16];
    const float* ncb = (const float*)d_in[17];
    const float* ecW = (const float*)d_in[18];
    const float* ecb = (const float*)d_in[19];

    float *eA, *eB, *n0, *n1, *ai_, *aj_, *nf_, *s_, *v_, *w_, *dv_;
    cudaGetSymbolAddress((void**)&eA, g_eA);
    cudaGetSymbolAddress((void**)&eB, g_eB);
    cudaGetSymbolAddress((void**)&n0, g_n0);
    cudaGetSymbolAddress((void**)&n1, g_n1);
    cudaGetSymbolAddress((void**)&ai_, g_ai);
    cudaGetSymbolAddress((void**)&aj_, g_aj);
    cudaGetSymbolAddress((void**)&nf_, g_nf);
    cudaGetSymbolAddress((void**)&s_, g_s);
    cudaGetSymbolAddress((void**)&v_, g_v);
    cudaGetSymbolAddress((void**)&w_, g_w);
    cudaGetSymbolAddress((void**)&dv_, g_dotv);

    float* out = (float*)d_out;
    float* out_nodes = out;
    float* out_edges = out + NODES_SZ;

    // ping-pong schedule; layer 2 writes land directly in d_out (no copies)
    float* ebuf[4] = {eA, eB, eA, out_edges};
    float* nbuf[4] = {n0, n1, n0, out_nodes};

    dim3 bs(16, 16);

    // initial projections
    gemm_small<<<dim3(16, 16), bs>>>(nodes_in, pnW, pnb, nbuf[0], 256, 256, 128, 128);
    edge_proj_mma<<<dim3(2, 256), 512>>>(edges_in, peW, 64, 64, peb, ebuf[0]);

    for (int l = 0; l < 3; l++) {
        const float* Wb_l  = Wb  + (size_t)l * 256 * 768;
        const float* Wbp_l = Wbp + (size_t)l * 65536;
        const float* Wfp_l = Wfp + (size_t)l * 65536;
        const float* ub_l  = ub  + l * 256;
        const float* Wf_l  = Wf  + (size_t)l * 65536;
        float* ecur = ebuf[l]; float* enxt = ebuf[l + 1];
        float* ncur = nbuf[l]; float* nnxt = nbuf[l + 1];

        vws_kernel<<<1, 256>>>(Wbp_l, Wfp_l, ub_l, ncur, v_, w_, s_);
        node3_mma<<<dim3(4, 4, 3), 128>>>(ncur, Wb_l, Wf_l, ai_, aj_, nf_);

        edge_fused<<<512, 512>>>(ecur, Wb_l + 256, ai_, aj_, adj,
                                 eln_g + l * 256, eln_b + l * 256, v_,
                                 enxt, dv_);
        attn_kernel<<<256, 256>>>(dv_, s_, nf_, adj, ncur,
                                  nln_g + l * 256, nln_b + l * 256, nnxt);
    }

    // final heads read directly from d_out regions
    gemm_small<<<dim3(7, 16), bs>>>(nbuf[3], ncW, ncb, out + NODES_SZ + EDGES_SZ,
                                    256, KN_, 256, 256);
    edge_logits_kernel<<<4096, 256>>>(ebuf[3], ecW, ecb,
                                      out + NODES_SZ + EDGES_SZ + 256 * KN_);
}

// round 12
// speedup vs baseline: 1.5489x; 1.0604x over previous
#include <cuda_runtime.h>
#include <cuda_fp16.h>
#include <cstdint>

#define Bb 2
#define Nn 128
#define Cc 256
#define BN2 (Bb*Nn*Nn)        // 32768 edge rows
#define NODES_SZ (Bb*Nn*Cc)   // 65536
#define EDGES_SZ (BN2*Cc)     // 8388608
#define KN_ 101
#define KE_ 7
#define ALPHA 0.2f
#define LN_EPS 1e-5f
#define NEG_BIG (-1e30f)

// ---------------- scratch (device globals: allocation-free) ----------------
__device__ float g_eA[EDGES_SZ];
__device__ float g_eB[EDGES_SZ];
__device__ float g_n0[NODES_SZ];
__device__ float g_n1[NODES_SZ];
__device__ float g_ai[NODES_SZ];
__device__ float g_aj[NODES_SZ];
__device__ float g_nf[NODES_SZ];
__device__ float g_s[Bb*Nn];
__device__ float g_v[Cc];
__device__ float g_w[Cc];
__device__ float g_dotv[BN2];

// ---------------- fp16 helpers ---------------------------------------------
// pack float4 -> 2 x half2 words (x->low of .x, y->high of .x, z/w in .y)
__device__ __forceinline__ uint2 f2h4(float4 v)
{
    __half2 lo = __floats2half2_rn(v.x, v.y);
    __half2 hi = __floats2half2_rn(v.z, v.w);
    uint2 r;
    r.x = *(unsigned*)&lo;
    r.y = *(unsigned*)&hi;
    return r;
}
// m16n8k16 f16 x f16 -> f32 accumulate
__device__ __forceinline__ void mma16n8k16(float& c0, float& c1, float& c2, float& c3,
                                           unsigned a0, unsigned a1, unsigned a2, unsigned a3,
                                           unsigned b0, unsigned b1)
{
    asm volatile("mma.sync.aligned.m16n8k16.row.col.f32.f16.f16.f32 "
                 "{%0,%1,%2,%3}, {%4,%5,%6,%7}, {%8,%9}, {%0,%1,%2,%3};"
                 : "+f"(c0), "+f"(c1), "+f"(c2), "+f"(c3)
                 : "r"(a0), "r"(a1), "r"(a2), "r"(a3), "r"(b0), "r"(b1));
}

// half2 words per row for a 32-half (BK=32) k-tile: 16 data + 2 pad
#define HSTR 18

// ---------------- small generic GEMM: out[m,n] = A[m,:]·W[n,:] + bias ------
__global__ void gemm_small(const float* __restrict__ A, const float* __restrict__ W,
                           const float* __restrict__ bias, float* __restrict__ out,
                           int M, int N, int K, int ldw)
{
    __shared__ float As[16][16];
    __shared__ float Ws[16][17];
    int tx = threadIdx.x, ty = threadIdx.y;
    int m = blockIdx.y * 16 + ty;
    int n = blockIdx.x * 16 + tx;
    float acc = 0.f;
    for (int k0 = 0; k0 < K; k0 += 16) {
        As[ty][tx] = (m < M) ? A[m * K + k0 + tx] : 0.f;
        int nn = blockIdx.x * 16 + ty;
        Ws[ty][tx] = (nn < N) ? W[(size_t)nn * ldw + k0 + tx] : 0.f;
        __syncthreads();
#pragma unroll
        for (int kk = 0; kk < 16; kk++) acc += As[ty][kk] * Ws[tx][kk];
        __syncthreads();
    }
    if (m < M && n < N) {
        float b = bias ? bias[n] : 0.f;
        out[m * N + n] = acc + b;
    }
}

// ---------------- edge projection GEMM (K=64): 512 thr, 128x128, fp16 ------
__global__ void __launch_bounds__(512)
edge_proj_mma(const float* __restrict__ A, const float* __restrict__ W,
              int K, int ldw, const float* __restrict__ bias, float* __restrict__ out)
{
    __shared__ unsigned As[128 * HSTR];
    __shared__ unsigned Bs[128 * HSTR];
    int tid = threadIdx.x;
    int lane = tid & 31, wid = tid >> 5;
    int warp_m = (wid & 3) * 32;
    int warp_n = (wid >> 2) * 32;
    int mbase = blockIdx.y * 128;
    int nbase = blockIdx.x * 128;
    int lg = lane >> 2, lt = lane & 3;

    float c[2][4][4];
#pragma unroll
    for (int mi = 0; mi < 2; mi++)
#pragma unroll
        for (int ni = 0; ni < 4; ni++)
#pragma unroll
            for (int q = 0; q < 4; q++) c[mi][ni][q] = 0.f;

    int lrow = tid >> 2;             // 0..127
    int lkw = (tid & 3) * 4;         // word offset 0,4,8,12 (k floats = lkw*2)
    const float* Aptr = A + (size_t)(mbase + lrow) * K + lkw * 2;
    const float* Wptr = W + (size_t)(nbase + lrow) * ldw + lkw * 2;
    unsigned* asw = &As[lrow * HSTR + lkw];
    unsigned* bsw = &Bs[lrow * HSTR + lkw];

    float4 ra[2], rb[2];
#pragma unroll
    for (int q = 0; q < 2; q++) {
        ra[q] = *(const float4*)(Aptr + 4 * q);
        rb[q] = *(const float4*)(Wptr + 4 * q);
    }

    for (int kt = 0; kt < K; kt += 32) {
#pragma unroll
        for (int q = 0; q < 2; q++) {
            *(uint2*)(asw + 2 * q) = f2h4(ra[q]);
            *(uint2*)(bsw + 2 * q) = f2h4(rb[q]);
        }
        __syncthreads();
        if (kt + 32 < K) {
#pragma unroll
            for (int q = 0; q < 2; q++) {
                ra[q] = *(const float4*)(Aptr + kt + 32 + 4 * q);
                rb[q] = *(const float4*)(Wptr + kt + 32 + 4 * q);
            }
        }
#pragma unroll
        for (int ks = 0; ks < 2; ks++) {
            int kw = ks * 8 + lt;
            unsigned af[2][4], bf[4][2];
#pragma unroll
            for (int mi = 0; mi < 2; mi++) {
                int r0 = warp_m + mi * 16 + lg;
                af[mi][0] = As[r0 * HSTR + kw];
                af[mi][1] = As[(r0 + 8) * HSTR + kw];
                af[mi][2] = As[r0 * HSTR + kw + 4];
                af[mi][3] = As[(r0 + 8) * HSTR + kw + 4];
            }
#pragma unroll
            for (int ni = 0; ni < 4; ni++) {
                int n0 = warp_n + ni * 8 + lg;
                bf[ni][0] = Bs[n0 * HSTR + kw];
                bf[ni][1] = Bs[n0 * HSTR + kw + 4];
            }
#pragma unroll
            for (int mi = 0; mi < 2; mi++)
#pragma unroll
                for (int ni = 0; ni < 4; ni++)
                    mma16n8k16(c[mi][ni][0], c[mi][ni][1], c[mi][ni][2], c[mi][ni][3],
                               af[mi][0], af[mi][1], af[mi][2], af[mi][3],
                               bf[ni][0], bf[ni][1]);
        }
        __syncthreads();
    }

#pragma unroll
    for (int mi = 0; mi < 2; mi++)
#pragma unroll
        for (int half = 0; half < 2; half++) {
            int m = mbase + warp_m + mi * 16 + lg + half * 8;
#pragma unroll
            for (int ni = 0; ni < 4; ni++) {
                int col = nbase + warp_n + ni * 8 + 2 * lt;
                float2 bv = *(const float2*)&bias[col];
                *(float2*)&out[(size_t)m * 256 + col] =
                    make_float2(c[mi][ni][2 * half + 0] + bv.x,
                                c[mi][ni][2 * half + 1] + bv.y);
            }
        }
}

// ---------------- node GEMMs: 64x64 tiles, 48 blocks, fp16 -----------------
__global__ void __launch_bounds__(128)
node3_mma(const float* __restrict__ A, const float* __restrict__ Wb_l,
          const float* __restrict__ Wf_l,
          float* __restrict__ ai, float* __restrict__ aj, float* __restrict__ nf)
{
    __shared__ unsigned As[64 * HSTR];
    __shared__ unsigned Bs[64 * HSTR];
    int z = blockIdx.z;
    const float* W = (z == 0) ? Wb_l : (z == 1) ? (Wb_l + 512) : Wf_l;
    int ldw = (z == 2) ? 256 : 768;
    float* out = (z == 0) ? ai : (z == 1) ? aj : nf;

    int tid = threadIdx.x;
    int lane = tid & 31, wid = tid >> 5;
    int warp_m = (wid & 1) * 32;
    int warp_n = (wid >> 1) * 32;
    int mbase = blockIdx.y * 64;
    int nbase = blockIdx.x * 64;
    int lg = lane >> 2, lt = lane & 3;

    float c[2][4][4];
#pragma unroll
    for (int mi = 0; mi < 2; mi++)
#pragma unroll
        for (int ni = 0; ni < 4; ni++)
#pragma unroll
            for (int q = 0; q < 4; q++) c[mi][ni][q] = 0.f;

    int lrow = tid >> 1;             // 0..63
    int lkw = (tid & 1) * 8;         // word offset 0 or 8 (k floats = lkw*2)
    const float* Aptr = A + (size_t)(mbase + lrow) * 256 + lkw * 2;
    const float* Wptr = W + (size_t)(nbase + lrow) * ldw + lkw * 2;
    unsigned* asw = &As[lrow * HSTR + lkw];
    unsigned* bsw = &Bs[lrow * HSTR + lkw];

    float4 ra[4], rb[4];
#pragma unroll
    for (int q = 0; q < 4; q++) {
        ra[q] = *(const float4*)(Aptr + 4 * q);
        rb[q] = *(const float4*)(Wptr + 4 * q);
    }

    for (int kt = 0; kt < 256; kt += 32) {
#pragma unroll
        for (int q = 0; q < 4; q++) {
            *(uint2*)(asw + 2 * q) = f2h4(ra[q]);
            *(uint2*)(bsw + 2 * q) = f2h4(rb[q]);
        }
        __syncthreads();
        if (kt + 32 < 256) {
#pragma unroll
            for (int q = 0; q < 4; q++) {
                ra[q] = *(const float4*)(Aptr + kt + 32 + 4 * q);
                rb[q] = *(const float4*)(Wptr + kt + 32 + 4 * q);
            }
        }
#pragma unroll
        for (int ks = 0; ks < 2; ks++) {
            int kw = ks * 8 + lt;
            unsigned af[2][4], bf[4][2];
#pragma unroll
            for (int mi = 0; mi < 2; mi++) {
                int r0 = warp_m + mi * 16 + lg;
                af[mi][0] = As[r0 * HSTR + kw];
                af[mi][1] = As[(r0 + 8) * HSTR + kw];
                af[mi][2] = As[r0 * HSTR + kw + 4];
                af[mi][3] = As[(r0 + 8) * HSTR + kw + 4];
            }
#pragma unroll
            for (int ni = 0; ni < 4; ni++) {
                int n0 = warp_n + ni * 8 + lg;
                bf[ni][0] = Bs[n0 * HSTR + kw];
                bf[ni][1] = Bs[n0 * HSTR + kw + 4];
            }
#pragma unroll
            for (int mi = 0; mi < 2; mi++)
#pragma unroll
                for (int ni = 0; ni < 4; ni++)
                    mma16n8k16(c[mi][ni][0], c[mi][ni][1], c[mi][ni][2], c[mi][ni][3],
                               af[mi][0], af[mi][1], af[mi][2], af[mi][3],
                               bf[ni][0], bf[ni][1]);
        }
        __syncthreads();
    }

#pragma unroll
    for (int mi = 0; mi < 2; mi++)
#pragma unroll
        for (int half = 0; half < 2; half++) {
            int m = mbase + warp_m + mi * 16 + lg + half * 8;
#pragma unroll
            for (int ni = 0; ni < 4; ni++) {
                int col = nbase + warp_n + ni * 8 + 2 * lt;
                *(float2*)&out[(size_t)m * 256 + col] =
                    make_float2(c[mi][ni][2 * half + 0], c[mi][ni][2 * half + 1]);
            }
        }
}

// ---------------- FUSED edge layer, 512 threads, fp16 ----------------------
// Tile 64 rows x 256 cols. 16 warps as 2m x 8n, warp tile 32x32.
// out = LN( lrelu(A@Wb2^T + ai + aj)*mask + A ) ; dotv[row] = out_row . v
__global__ void __launch_bounds__(512)
edge_fused(const float* __restrict__ A, const float* __restrict__ W,
           const float* __restrict__ ai, const float* __restrict__ aj,
           const float* __restrict__ mask,
           const float* __restrict__ lng, const float* __restrict__ lnb,
           const float* __restrict__ v,
           float* __restrict__ out, float* __restrict__ dotv)
{
    __shared__ unsigned As[64 * HSTR];     // 4608 B; reused as reduction scratch
    __shared__ unsigned Bs[256 * HSTR];    // 18432 B
    float* red = (float*)As;

    int tid = threadIdx.x;
    int lane = tid & 31, wid = tid >> 5;
    int wm = wid & 1;          // 2 m-warps (32 rows each)
    int wn = wid >> 1;         // 8 n-warps (32 cols each)
    int warp_m = wm * 32;
    int warp_n = wn * 32;
    int mbase = blockIdx.x * 64;
    int lg = lane >> 2, lt = lane & 3;

    float c[2][4][4];
#pragma unroll
    for (int mi = 0; mi < 2; mi++)
#pragma unroll
        for (int ni = 0; ni < 4; ni++)
#pragma unroll
            for (int q = 0; q < 4; q++) c[mi][ni][q] = 0.f;

    // loaders: A 64 rows x 16 words (8 thr/row, 2 words each);
    //          B 256 rows x 16 words (4 passes of 64 rows)
    int arow = tid >> 3;             // 0..63
    int akw = (tid & 7) * 2;         // word offset 0..14 (k floats = akw*2)
    const float* Ap = A + (size_t)(mbase + arow) * 256 + akw * 2;
    unsigned* asw = &As[arow * HSTR + akw];
    const float* Wp = W + (size_t)arow * 768 + akw * 2;

    float4 ra, rb[4];
    ra = *(const float4*)Ap;
#pragma unroll
    for (int rr = 0; rr < 4; rr++)
        rb[rr] = *(const float4*)(Wp + (size_t)rr * 64 * 768);

    for (int kt = 0; kt < 256; kt += 32) {
        *(uint2*)asw = f2h4(ra);
#pragma unroll
        for (int rr = 0; rr < 4; rr++)
            *(uint2*)&Bs[(rr * 64 + arow) * HSTR + akw] = f2h4(rb[rr]);
        __syncthreads();
        if (kt + 32 < 256) {
            ra = *(const float4*)(Ap + kt + 32);
#pragma unroll
            for (int rr = 0; rr < 4; rr++)
                rb[rr] = *(const float4*)(Wp + (size_t)rr * 64 * 768 + kt + 32);
        }
#pragma unroll
        for (int ks = 0; ks < 2; ks++) {
            int kw = ks * 8 + lt;
            unsigned af[2][4], bf[4][2];
#pragma unroll
            for (int mi = 0; mi < 2; mi++) {
                int r0 = warp_m + mi * 16 + lg;
                af[mi][0] = As[r0 * HSTR + kw];
                af[mi][1] = As[(r0 + 8) * HSTR + kw];
                af[mi][2] = As[r0 * HSTR + kw + 4];
                af[mi][3] = As[(r0 + 8) * HSTR + kw + 4];
            }
#pragma unroll
            for (int ni = 0; ni < 4; ni++) {
                int n0 = warp_n + ni * 8 + lg;
                bf[ni][0] = Bs[n0 * HSTR + kw];
                bf[ni][1] = Bs[n0 * HSTR + kw + 4];
            }
#pragma unroll
            for (int mi = 0; mi < 2; mi++)
#pragma unroll
                for (int ni = 0; ni < 4; ni++)
                    mma16n8k16(c[mi][ni][0], c[mi][ni][1], c[mi][ni][2], c[mi][ni][3],
                               af[mi][0], af[mi][1], af[mi][2], af[mi][3],
                               bf[ni][0], bf[ni][1]);
        }
        __syncthreads();
    }

    // ---- epilogue phase 1: h = lrelu(acc+ai+aj)*mask + residual; row stats
    // red layout: rs [0,512), rq [512,1024), mean [1024,1088), inv [1088,1152)
#pragma unroll
    for (int mi = 0; mi < 2; mi++) {
#pragma unroll
        for (int half = 0; half < 2; half++) {
            int rloc = warp_m + mi * 16 + half * 8 + lg;    // 0..63
            int m = mbase + rloc;
            int b = m >> 14;
            int i = (m >> 7) & 127;
            int j = m & 127;
            float mv = mask[m];
            const float* aip = &ai[(size_t)((b << 7) + i) * 256];
            const float* ajp = &aj[(size_t)((b << 7) + j) * 256];
            const float* res = &A[(size_t)m * 256];
            float rs = 0.f, rq = 0.f;
#pragma unroll
            for (int ni = 0; ni < 4; ni++) {
                int col = warp_n + ni * 8 + 2 * lt;
                float2 a2 = *(const float2*)&aip[col];
                float2 j2 = *(const float2*)&ajp[col];
                float2 r2 = *(const float2*)&res[col];
                float v0 = c[mi][ni][2 * half + 0] + a2.x + j2.x;
                float v1 = c[mi][ni][2 * half + 1] + a2.y + j2.y;
                v0 = (v0 > 0.f ? v0 : ALPHA * v0) * mv + r2.x;
                v1 = (v1 > 0.f ? v1 : ALPHA * v1) * mv + r2.y;
                c[mi][ni][2 * half + 0] = v0;
                c[mi][ni][2 * half + 1] = v1;
                rs += v0 + v1;
                rq += v0 * v0 + v1 * v1;
            }
            rs += __shfl_xor_sync(0xffffffffu, rs, 1);
            rs += __shfl_xor_sync(0xffffffffu, rs, 2);
            rq += __shfl_xor_sync(0xffffffffu, rq, 1);
            rq += __shfl_xor_sync(0xffffffffu, rq, 2);
            if (lt == 0) {
                red[wn * 64 + rloc] = rs;
                red[512 + wn * 64 + rloc] = rq;
            }
        }
    }
    __syncthreads();
    if (tid < 64) {
        float S = 0.f, Q = 0.f;
#pragma unroll
        for (int w8 = 0; w8 < 8; w8++) {
            S += red[w8 * 64 + tid];
            Q += red[512 + w8 * 64 + tid];
        }
        float mean = S * (1.f / 256.f);
        float var = Q * (1.f / 256.f) - mean * mean;
        red[1024 + tid] = mean;
        red[1088 + tid] = rsqrtf(var + LN_EPS);
    }
    __syncthreads();

    // ---- epilogue phase 2: normalize, store, dot with v
#pragma unroll
    for (int mi = 0; mi < 2; mi++) {
#pragma unroll
        for (int half = 0; half < 2; half++) {
            int rloc = warp_m + mi * 16 + half * 8 + lg;
            int m = mbase + rloc;
            float mean = red[1024 + rloc];
            float inv = red[1088 + rloc];
            float dvp = 0.f;
#pragma unroll
            for (int ni = 0; ni < 4; ni++) {
                int col = warp_n + ni * 8 + 2 * lt;
                float2 g2 = *(const float2*)&lng[col];
                float2 b2 = *(const float2*)&lnb[col];
                float2 v2 = *(const float2*)&v[col];
                float y0 = (c[mi][ni][2 * half + 0] - mean) * inv * g2.x + b2.x;
                float y1 = (c[mi][ni][2 * half + 1] - mean) * inv * g2.y + b2.y;
                *(float2*)&out[(size_t)m * 256 + col] = make_float2(y0, y1);
                dvp += y0 * v2.x + y1 * v2.y;
            }
            dvp += __shfl_xor_sync(0xffffffffu, dvp, 1);
            dvp += __shfl_xor_sync(0xffffffffu, dvp, 2);
            if (lt == 0) red[wn * 64 + rloc] = dvp;   // stats at 1024+ untouched
        }
    }
    __syncthreads();
    if (tid < 64) {
        float S = 0.f;
#pragma unroll
        for (int w8 = 0; w8 < 8; w8++) S += red[w8 * 64 + tid];
        dotv[mbase + tid] = S;
    }
}

// ---------------- v = Wbp^T ub, w = Wfp^T ub, s = nodes·w (merged) ---------
__global__ void vws_kernel(const float* __restrict__ Wbp, const float* __restrict__ Wfp,
                           const float* __restrict__ ub, const float* __restrict__ nodes,
                           float* __restrict__ v, float* __restrict__ w,
                           float* __restrict__ s)
{
    __shared__ float ws[256];
    int k = threadIdx.x;
    float a = 0.f, b = 0.f;
    for (int c = 0; c < 256; c++) {
        float u = ub[c];
        a += u * Wbp[c * 256 + k];
        b += u * Wfp[c * 256 + k];
    }
    v[k] = a; w[k] = b;
    ws[k] = b;
    __syncthreads();
    float acc = 0.f;
    const float* rp = nodes + (size_t)k * 256;
    for (int c = 0; c < 256; c++) acc += rp[c] * ws[c];
    s[k] = acc;
}

// ---------------- attention + node update (LN fused) -----------------------
__global__ void __launch_bounds__(256)
attn_kernel(const float* __restrict__ dotv, const float* __restrict__ s,
            const float* __restrict__ nf, const float* __restrict__ mask,
            const float* __restrict__ nodes_old, const float* __restrict__ g,
            const float* __restrict__ bt, float* __restrict__ nodes_new)
{
    int bi = blockIdx.x;
    int b = bi >> 7, i = bi & 127;
    int t = threadIdx.x;
    __shared__ float sm_a[128];
    __shared__ float sred1[8], sred2[8];
    __shared__ float sm_m, sm_sum, sm_mean, sm_inv;

    if (t < 128) {
        int j = t;
        float mv = mask[b * 16384 + i * 128 + j];
        float r;
        if (mv > 0.f) {
            float dv = dotv[b * 16384 + j * 128 + i];
            r = dv + s[b * 128 + i] + s[b * 128 + j];
            r = r > 0.f ? r : ALPHA * r;
        } else {
            r = NEG_BIG;
        }
        sm_a[j] = r;
    }
    __syncthreads();
    if (t < 32) {
        float m = fmaxf(fmaxf(sm_a[t], sm_a[t + 32]), fmaxf(sm_a[t + 64], sm_a[t + 96]));
#pragma unroll
        for (int o = 16; o; o >>= 1) m = fmaxf(m, __shfl_xor_sync(0xffffffffu, m, o));
        if (t == 0) sm_m = m;
    }
    __syncthreads();
    if (t < 128) sm_a[t] = expf(sm_a[t] - sm_m);
    __syncthreads();
    if (t < 32) {
        float su = sm_a[t] + sm_a[t + 32] + sm_a[t + 64] + sm_a[t + 96];
#pragma unroll
        for (int o = 16; o; o >>= 1) su += __shfl_xor_sync(0xffffffffu, su, o);
        if (t == 0) sm_sum = su;
    }
    __syncthreads();
    float inv_sum = 1.f / sm_sum;

    int c = t;
    float acc = 0.f;
    const float* nfb = nf + (size_t)b * Nn * Cc + c;
#pragma unroll 4
    for (int j = 0; j < 128; j++) acc += sm_a[j] * nfb[(size_t)j * Cc];
    acc *= inv_sum;
    float h = (acc > 0.f ? acc : ALPHA * acc) + nodes_old[(size_t)(b * 128 + i) * 256 + c];

    int lane = t & 31, wp = t >> 5;
    float su = h, sq = h * h;
#pragma unroll
    for (int o = 16; o; o >>= 1) {
        su += __shfl_xor_sync(0xffffffffu, su, o);
        sq += __shfl_xor_sync(0xffffffffu, sq, o);
    }
    if (lane == 0) { sred1[wp] = su; sred2[wp] = sq; }
    __syncthreads();
    if (t == 0) {
        float S = 0.f, Q = 0.f;
#pragma unroll
        for (int w2 = 0; w2 < 8; w2++) { S += sred1[w2]; Q += sred2[w2]; }
        float mean = S * (1.f / 256.f);
        float var = Q * (1.f / 256.f) - mean * mean;
        sm_mean = mean;
        sm_inv = rsqrtf(var + LN_EPS);
    }
    __syncthreads();
    nodes_new[(size_t)(b * 128 + i) * 256 + c] = (h - sm_mean) * sm_inv * g[c] + bt[c];
}

// ---------------- edge logits: out[row,k] = e[row]·ecW[k] + ecb[k] ---------
__global__ void edge_logits_kernel(const float* __restrict__ e, const float* __restrict__ W,
                                   const float* __restrict__ bias, float* __restrict__ out)
{
    int warp = threadIdx.x >> 5, lane = threadIdx.x & 31;
    int row = blockIdx.x * 8 + warp;
    const float* rp = e + (size_t)row * 256;
    float x[8];
#pragma unroll
    for (int q = 0; q < 8; q++) x[q] = rp[lane + q * 32];
#pragma unroll
    for (int k = 0; k < KE_; k++) {
        float acc = 0.f;
#pragma unroll
        for (int q = 0; q < 8; q++) acc += x[q] * W[k * 256 + lane + q * 32];
#pragma unroll
        for (int o = 16; o; o >>= 1) acc += __shfl_xor_sync(0xffffffffu, acc, o);
        if (lane == 0) out[(size_t)row * KE_ + k] = acc + bias[k];
    }
}

// ---------------- host ------------------------------------------------------
extern "C" void kernel_launch(void* const* d_in, const int* in_sizes, int n_in,
                              void* d_out, int out_size)
{
    const float* nodes_in = (const float*)d_in[0];
    const float* edges_in = (const float*)d_in[1];
    const float* adj      = (const float*)d_in[2];
    const float* pnW = (const float*)d_in[3];
    const float* pnb = (const float*)d_in[4];
    const float* peW = (const float*)d_in[5];
    const float* peb = (const float*)d_in[6];
    const float* Wb  = (const float*)d_in[7];
    const float* Wbp = (const float*)d_in[8];
    const float* Wfp = (const float*)d_in[9];
    const float* ub  = (const float*)d_in[10];
    const float* Wf  = (const float*)d_in[11];
    const float* eln_g = (const float*)d_in[12];
    const float* eln_b = (const float*)d_in[13];
    const float* nln_g = (const float*)d_in[14];
    const float* nln_b = (const float*)d_in[15];
    const float* ncW = (const float*)d_in[16];
    const float* ncb = (const float*)d_in[17];
    const float* ecW = (const float*)d_in[18];
    const float* ecb = (const float*)d_in[19];

    float *eA, *eB, *n0, *n1, *ai_, *aj_, *nf_, *s_, *v_, *w_, *dv_;
    cudaGetSymbolAddress((void**)&eA, g_eA);
    cudaGetSymbolAddress((void**)&eB, g_eB);
    cudaGetSymbolAddress((void**)&n0, g_n0);
    cudaGetSymbolAddress((void**)&n1, g_n1);
    cudaGetSymbolAddress((void**)&ai_, g_ai);
    cudaGetSymbolAddress((void**)&aj_, g_aj);
    cudaGetSymbolAddress((void**)&nf_, g_nf);
    cudaGetSymbolAddress((void**)&s_, g_s);
    cudaGetSymbolAddress((void**)&v_, g_v);
    cudaGetSymbolAddress((void**)&w_, g_w);
    cudaGetSymbolAddress((void**)&dv_, g_dotv);

    float* out = (float*)d_out;
    float* out_nodes = out;
    float* out_edges = out + NODES_SZ;

    // ping-pong schedule; layer 2 writes land directly in d_out (no copies)
    float* ebuf[4] = {eA, eB, eA, out_edges};
    float* nbuf[4] = {n0, n1, n0, out_nodes};

    dim3 bs(16, 16);

    // initial projections
    gemm_small<<<dim3(16, 16), bs>>>(nodes_in, pnW, pnb, nbuf[0], 256, 256, 128, 128);
    edge_proj_mma<<<dim3(2, 256), 512>>>(edges_in, peW, 64, 64, peb, ebuf[0]);

    for (int l = 0; l < 3; l++) {
        const float* Wb_l  = Wb  + (size_t)l * 256 * 768;
        const float* Wbp_l = Wbp + (size_t)l * 65536;
        const float* Wfp_l = Wfp + (size_t)l * 65536;
        const float* ub_l  = ub  + l * 256;
        const float* Wf_l  = Wf  + (size_t)l * 65536;
        float* ecur = ebuf[l]; float* enxt = ebuf[l + 1];
        float* ncur = nbuf[l]; float* nnxt = nbuf[l + 1];

        vws_kernel<<<1, 256>>>(Wbp_l, Wfp_l, ub_l, ncur, v_, w_, s_);
        node3_mma<<<dim3(4, 4, 3), 128>>>(ncur, Wb_l, Wf_l, ai_, aj_, nf_);

        edge_fused<<<512, 512>>>(ecur, Wb_l + 256, ai_, aj_, adj,
                                 eln_g + l * 256, eln_b + l * 256, v_,
                                 enxt, dv_);
        attn_kernel<<<256, 256>>>(dv_, s_, nf_, adj, ncur,
                                  nln_g + l * 256, nln_b + l * 256, nnxt);
    }

    // final heads read directly from d_out regions
    gemm_small<<<dim3(7, 16), bs>>>(nbuf[3], ncW, ncb, out + NODES_SZ + EDGES_SZ,
                                    256, KN_, 256, 256);
    edge_logits_kernel<<<4096, 256>>>(ebuf[3], ecW, ecb,
                                      out + NODES_SZ + EDGES_SZ + 256 * KN_);
}

// round 13
// speedup vs baseline: 1.6521x; 1.0667x over previous
#include <cuda_runtime.h>
#include <cuda_fp16.h>
#include <cstdint>

#define Bb 2
#define Nn 128
#define Cc 256
#define BN2 (Bb*Nn*Nn)        // 32768 edge rows
#define NODES_SZ (Bb*Nn*Cc)   // 65536
#define EDGES_SZ (BN2*Cc)     // 8388608
#define KN_ 101
#define KE_ 7
#define ALPHA 0.2f
#define LN_EPS 1e-5f
#define NEG_BIG (-1e30f)

// ---------------- scratch (device globals: allocation-free) ----------------
__device__ float g_eA[EDGES_SZ];
__device__ float g_eB[EDGES_SZ];
__device__ float g_n0[NODES_SZ];
__device__ float g_n1[NODES_SZ];
__device__ float g_ai[NODES_SZ];
__device__ float g_aj[NODES_SZ];
__device__ float g_nf[NODES_SZ];
__device__ float g_s[Bb*Nn];
__device__ float g_v[Cc];
__device__ float g_w[Cc];
__device__ float g_dotv[BN2];

// ---------------- fp16 helpers ---------------------------------------------
__device__ __forceinline__ uint2 f2h4(float4 v)
{
    __half2 lo = __floats2half2_rn(v.x, v.y);
    __half2 hi = __floats2half2_rn(v.z, v.w);
    uint2 r;
    r.x = *(unsigned*)&lo;
    r.y = *(unsigned*)&hi;
    return r;
}
__device__ __forceinline__ void mma16n8k16(float& c0, float& c1, float& c2, float& c3,
                                           unsigned a0, unsigned a1, unsigned a2, unsigned a3,
                                           unsigned b0, unsigned b1)
{
    asm volatile("mma.sync.aligned.m16n8k16.row.col.f32.f16.f16.f32 "
                 "{%0,%1,%2,%3}, {%4,%5,%6,%7}, {%8,%9}, {%0,%1,%2,%3};"
                 : "+f"(c0), "+f"(c1), "+f"(c2), "+f"(c3)
                 : "r"(a0), "r"(a1), "r"(a2), "r"(a3), "r"(b0), "r"(b1));
}
__device__ __forceinline__ void ldsm_x4(unsigned r[4], uint32_t addr)
{
    asm volatile("ldmatrix.sync.aligned.m8n8.x4.shared.b16 {%0,%1,%2,%3}, [%4];"
                 : "=r"(r[0]), "=r"(r[1]), "=r"(r[2]), "=r"(r[3]) : "r"(addr));
}
__device__ __forceinline__ uint32_t smem_u32(const void* p)
{
    uint32_t a;
    asm("{ .reg .u64 t; cvta.to.shared.u64 t, %1; cvt.u32.u64 %0, t; }"
        : "=r"(a) : "l"(p));
    return a;
}

// half2-words per row for a 32-half k-tile: 16 data + 4 pad = 20 (80B rows)
// bank walk 20*r mod 32 = {0,20,8,28,16,4,24,12} -> conflict-free LDSM
#define HSTR 20
#define HROWB 80

// ---------------- small generic GEMM: out[m,n] = A[m,:]·W[n,:] + bias ------
__global__ void gemm_small(const float* __restrict__ A, const float* __restrict__ W,
                           const float* __restrict__ bias, float* __restrict__ out,
                           int M, int N, int K, int ldw)
{
    __shared__ float As[16][16];
    __shared__ float Ws[16][17];
    int tx = threadIdx.x, ty = threadIdx.y;
    int m = blockIdx.y * 16 + ty;
    int n = blockIdx.x * 16 + tx;
    float acc = 0.f;
    for (int k0 = 0; k0 < K; k0 += 16) {
        As[ty][tx] = (m < M) ? A[m * K + k0 + tx] : 0.f;
        int nn = blockIdx.x * 16 + ty;
        Ws[ty][tx] = (nn < N) ? W[(size_t)nn * ldw + k0 + tx] : 0.f;
        __syncthreads();
#pragma unroll
        for (int kk = 0; kk < 16; kk++) acc += As[ty][kk] * Ws[tx][kk];
        __syncthreads();
    }
    if (m < M && n < N) {
        float b = bias ? bias[n] : 0.f;
        out[m * N + n] = acc + b;
    }
}

// ---------------- edge projection GEMM (K=64): 512 thr, 128x128, LDSM ------
__global__ void __launch_bounds__(512)
edge_proj_mma(const float* __restrict__ A, const float* __restrict__ W,
              int K, int ldw, const float* __restrict__ bias, float* __restrict__ out)
{
    __shared__ unsigned As[128 * HSTR];
    __shared__ unsigned Bs[128 * HSTR];
    int tid = threadIdx.x;
    int lane = tid & 31, wid = tid >> 5;
    int warp_m = (wid & 3) * 32;
    int warp_n = (wid >> 2) * 32;
    int mbase = blockIdx.y * 128;
    int nbase = blockIdx.x * 128;
    int lg = lane >> 2, lt = lane & 3;

    float c[2][4][4];
#pragma unroll
    for (int mi = 0; mi < 2; mi++)
#pragma unroll
        for (int ni = 0; ni < 4; ni++)
#pragma unroll
            for (int q = 0; q < 4; q++) c[mi][ni][q] = 0.f;

    int lrow = tid >> 2;             // 0..127
    int lkw = (tid & 3) * 4;         // word offset 0,4,8,12
    const float* Aptr = A + (size_t)(mbase + lrow) * K + lkw * 2;
    const float* Wptr = W + (size_t)(nbase + lrow) * ldw + lkw * 2;
    unsigned* asw = &As[lrow * HSTR + lkw];
    unsigned* bsw = &Bs[lrow * HSTR + lkw];

    uint32_t abase = smem_u32(As), bbase = smem_u32(Bs);
    uint32_t a_off = (uint32_t)(warp_m + (lane & 15)) * HROWB + (lane >> 4) * 16;
    uint32_t b_off = (uint32_t)(warp_n + ((lane >> 4) << 3) + (lane & 7)) * HROWB
                   + ((lane >> 3) & 1) * 16;

    float4 ra[2], rb[2];
#pragma unroll
    for (int q = 0; q < 2; q++) {
        ra[q] = *(const float4*)(Aptr + 4 * q);
        rb[q] = *(const float4*)(Wptr + 4 * q);
    }

    for (int kt = 0; kt < K; kt += 32) {
#pragma unroll
        for (int q = 0; q < 2; q++) {
            *(uint2*)(asw + 2 * q) = f2h4(ra[q]);
            *(uint2*)(bsw + 2 * q) = f2h4(rb[q]);
        }
        __syncthreads();
        if (kt + 32 < K) {
#pragma unroll
            for (int q = 0; q < 2; q++) {
                ra[q] = *(const float4*)(Aptr + kt + 32 + 4 * q);
                rb[q] = *(const float4*)(Wptr + kt + 32 + 4 * q);
            }
        }
        unsigned af[2][2][4], bf[2][2][4];
#pragma unroll
        for (int mi = 0; mi < 2; mi++)
#pragma unroll
            for (int ks = 0; ks < 2; ks++)
                ldsm_x4(af[mi][ks], abase + a_off + mi * 16 * HROWB + ks * 32);
#pragma unroll
        for (int p = 0; p < 2; p++)
#pragma unroll
            for (int ks = 0; ks < 2; ks++)
                ldsm_x4(bf[p][ks], bbase + b_off + p * 16 * HROWB + ks * 32);
#pragma unroll
        for (int ks = 0; ks < 2; ks++)
#pragma unroll
            for (int mi = 0; mi < 2; mi++)
#pragma unroll
                for (int p = 0; p < 2; p++) {
                    mma16n8k16(c[mi][2*p][0], c[mi][2*p][1], c[mi][2*p][2], c[mi][2*p][3],
                               af[mi][ks][0], af[mi][ks][1], af[mi][ks][2], af[mi][ks][3],
                               bf[p][ks][0], bf[p][ks][1]);
                    mma16n8k16(c[mi][2*p+1][0], c[mi][2*p+1][1], c[mi][2*p+1][2], c[mi][2*p+1][3],
                               af[mi][ks][0], af[mi][ks][1], af[mi][ks][2], af[mi][ks][3],
                               bf[p][ks][2], bf[p][ks][3]);
                }
        __syncthreads();
    }

#pragma unroll
    for (int mi = 0; mi < 2; mi++)
#pragma unroll
        for (int half = 0; half < 2; half++) {
            int m = mbase + warp_m + mi * 16 + lg + half * 8;
#pragma unroll
            for (int ni = 0; ni < 4; ni++) {
                int col = nbase + warp_n + ni * 8 + 2 * lt;
                float2 bv = *(const float2*)&bias[col];
                *(float2*)&out[(size_t)m * 256 + col] =
                    make_float2(c[mi][ni][2 * half + 0] + bv.x,
                                c[mi][ni][2 * half + 1] + bv.y);
            }
        }
}

// ---------------- node GEMMs: 64x64 tiles, 48 blocks, LDSM -----------------
__global__ void __launch_bounds__(128)
node3_mma(const float* __restrict__ A, const float* __restrict__ Wb_l,
          const float* __restrict__ Wf_l,
          float* __restrict__ ai, float* __restrict__ aj, float* __restrict__ nf)
{
    __shared__ unsigned As[64 * HSTR];
    __shared__ unsigned Bs[64 * HSTR];
    int z = blockIdx.z;
    const float* W = (z == 0) ? Wb_l : (z == 1) ? (Wb_l + 512) : Wf_l;
    int ldw = (z == 2) ? 256 : 768;
    float* out = (z == 0) ? ai : (z == 1) ? aj : nf;

    int tid = threadIdx.x;
    int lane = tid & 31, wid = tid >> 5;
    int warp_m = (wid & 1) * 32;
    int warp_n = (wid >> 1) * 32;
    int mbase = blockIdx.y * 64;
    int nbase = blockIdx.x * 64;
    int lg = lane >> 2, lt = lane & 3;

    float c[2][4][4];
#pragma unroll
    for (int mi = 0; mi < 2; mi++)
#pragma unroll
        for (int ni = 0; ni < 4; ni++)
#pragma unroll
            for (int q = 0; q < 4; q++) c[mi][ni][q] = 0.f;

    int lrow = tid >> 1;             // 0..63
    int lkw = (tid & 1) * 8;         // word offset 0 or 8
    const float* Aptr = A + (size_t)(mbase + lrow) * 256 + lkw * 2;
    const float* Wptr = W + (size_t)(nbase + lrow) * ldw + lkw * 2;
    unsigned* asw = &As[lrow * HSTR + lkw];
    unsigned* bsw = &Bs[lrow * HSTR + lkw];

    uint32_t abase = smem_u32(As), bbase = smem_u32(Bs);
    uint32_t a_off = (uint32_t)(warp_m + (lane & 15)) * HROWB + (lane >> 4) * 16;
    uint32_t b_off = (uint32_t)(warp_n + ((lane >> 4) << 3) + (lane & 7)) * HROWB
                   + ((lane >> 3) & 1) * 16;

    float4 ra[4], rb[4];
#pragma unroll
    for (int q = 0; q < 4; q++) {
        ra[q] = *(const float4*)(Aptr + 4 * q);
        rb[q] = *(const float4*)(Wptr + 4 * q);
    }

    for (int kt = 0; kt < 256; kt += 32) {
#pragma unroll
        for (int q = 0; q < 4; q++) {
            *(uint2*)(asw + 2 * q) = f2h4(ra[q]);
            *(uint2*)(bsw + 2 * q) = f2h4(rb[q]);
        }
        __syncthreads();
        if (kt + 32 < 256) {
#pragma unroll
            for (int q = 0; q < 4; q++) {
                ra[q] = *(const float4*)(Aptr + kt + 32 + 4 * q);
                rb[q] = *(const float4*)(Wptr + kt + 32 + 4 * q);
            }
        }
        unsigned af[2][2][4], bf[2][2][4];
#pragma unroll
        for (int mi = 0; mi < 2; mi++)
#pragma unroll
            for (int ks = 0; ks < 2; ks++)
                ldsm_x4(af[mi][ks], abase + a_off + mi * 16 * HROWB + ks * 32);
#pragma unroll
        for (int p = 0; p < 2; p++)
#pragma unroll
            for (int ks = 0; ks < 2; ks++)
                ldsm_x4(bf[p][ks], bbase + b_off + p * 16 * HROWB + ks * 32);
#pragma unroll
        for (int ks = 0; ks < 2; ks++)
#pragma unroll
            for (int mi = 0; mi < 2; mi++)
#pragma unroll
                for (int p = 0; p < 2; p++) {
                    mma16n8k16(c[mi][2*p][0], c[mi][2*p][1], c[mi][2*p][2], c[mi][2*p][3],
                               af[mi][ks][0], af[mi][ks][1], af[mi][ks][2], af[mi][ks][3],
                               bf[p][ks][0], bf[p][ks][1]);
                    mma16n8k16(c[mi][2*p+1][0], c[mi][2*p+1][1], c[mi][2*p+1][2], c[mi][2*p+1][3],
                               af[mi][ks][0], af[mi][ks][1], af[mi][ks][2], af[mi][ks][3],
                               bf[p][ks][2], bf[p][ks][3]);
                }
        __syncthreads();
    }

#pragma unroll
    for (int mi = 0; mi < 2; mi++)
#pragma unroll
        for (int half = 0; half < 2; half++) {
            int m = mbase + warp_m + mi * 16 + lg + half * 8;
#pragma unroll
            for (int ni = 0; ni < 4; ni++) {
                int col = nbase + warp_n + ni * 8 + 2 * lt;
                *(float2*)&out[(size_t)m * 256 + col] =
                    make_float2(c[mi][ni][2 * half + 0], c[mi][ni][2 * half + 1]);
            }
        }
}

// ---------------- FUSED edge layer: 512 thr, LDSM, double-buffered ---------
// Tile 64 rows x 256 cols. 16 warps as 2m x 8n, warp tile 32x32.
// Dynamic smem: As[2] (1280 w each) + Bs[2] (5120 w each) = 51200 B.
// One __syncthreads per k-tile.
#define EF_DSMEM (2 * (64 * HSTR) * 4 + 2 * (256 * HSTR) * 4)
__global__ void __launch_bounds__(512)
edge_fused(const float* __restrict__ A, const float* __restrict__ W,
           const float* __restrict__ ai, const float* __restrict__ aj,
           const float* __restrict__ mask,
           const float* __restrict__ lng, const float* __restrict__ lnb,
           const float* __restrict__ v,
           float* __restrict__ out, float* __restrict__ dotv)
{
    extern __shared__ unsigned dyn[];
    unsigned* Asb[2] = {dyn, dyn + 64 * HSTR};
    unsigned* Bsb[2] = {dyn + 2 * 64 * HSTR, dyn + 2 * 64 * HSTR + 256 * HSTR};
    float* red = (float*)dyn;            // reused post-GEMM (needs 1152 floats)

    int tid = threadIdx.x;
    int lane = tid & 31, wid = tid >> 5;
    int wm = wid & 1;          // 2 m-warps (32 rows each)
    int wn = wid >> 1;         // 8 n-warps (32 cols each)
    int warp_m = wm * 32;
    int warp_n = wn * 32;
    int mbase = blockIdx.x * 64;
    int lg = lane >> 2, lt = lane & 3;

    float c[2][4][4];
#pragma unroll
    for (int mi = 0; mi < 2; mi++)
#pragma unroll
        for (int ni = 0; ni < 4; ni++)
#pragma unroll
            for (int q = 0; q < 4; q++) c[mi][ni][q] = 0.f;

    // loaders: A 64 rows (8 thr/row), B 256 rows (4 passes of 64)
    int arow = tid >> 3;             // 0..63
    int akw = (tid & 7) * 2;         // word offset 0..14
    const float* Ap = A + (size_t)(mbase + arow) * 256 + akw * 2;
    const float* Wp = W + (size_t)arow * 768 + akw * 2;

    uint32_t abase[2] = {smem_u32(Asb[0]), smem_u32(Asb[1])};
    uint32_t bbase[2] = {smem_u32(Bsb[0]), smem_u32(Bsb[1])};
    uint32_t a_off = (uint32_t)(warp_m + (lane & 15)) * HROWB + (lane >> 4) * 16;
    uint32_t b_off = (uint32_t)(warp_n + ((lane >> 4) << 3) + (lane & 7)) * HROWB
                   + ((lane >> 3) & 1) * 16;

    // prologue: tile 0 -> buffer 0
    {
        float4 ra = *(const float4*)Ap;
        *(uint2*)&Asb[0][arow * HSTR + akw] = f2h4(ra);
#pragma unroll
        for (int rr = 0; rr < 4; rr++) {
            float4 rb = *(const float4*)(Wp + (size_t)rr * 64 * 768);
            *(uint2*)&Bsb[0][(rr * 64 + arow) * HSTR + akw] = f2h4(rb);
        }
    }
    __syncthreads();

    int cur = 0;
    for (int kt = 0; kt < 256; kt += 32) {
        bool more = (kt + 32) < 256;
        float4 ra; float4 rb[4];
        if (more) {
            ra = *(const float4*)(Ap + kt + 32);
#pragma unroll
            for (int rr = 0; rr < 4; rr++)
                rb[rr] = *(const float4*)(Wp + (size_t)rr * 64 * 768 + kt + 32);
        }
        unsigned af[2][2][4], bf[2][2][4];
#pragma unroll
        for (int mi = 0; mi < 2; mi++)
#pragma unroll
            for (int ks = 0; ks < 2; ks++)
                ldsm_x4(af[mi][ks], abase[cur] + a_off + mi * 16 * HROWB + ks * 32);
#pragma unroll
        for (int p = 0; p < 2; p++)
#pragma unroll
            for (int ks = 0; ks < 2; ks++)
                ldsm_x4(bf[p][ks], bbase[cur] + b_off + p * 16 * HROWB + ks * 32);
#pragma unroll
        for (int ks = 0; ks < 2; ks++)
#pragma unroll
            for (int mi = 0; mi < 2; mi++)
#pragma unroll
                for (int p = 0; p < 2; p++) {
                    mma16n8k16(c[mi][2*p][0], c[mi][2*p][1], c[mi][2*p][2], c[mi][2*p][3],
                               af[mi][ks][0], af[mi][ks][1], af[mi][ks][2], af[mi][ks][3],
                               bf[p][ks][0], bf[p][ks][1]);
                    mma16n8k16(c[mi][2*p+1][0], c[mi][2*p+1][1], c[mi][2*p+1][2], c[mi][2*p+1][3],
                               af[mi][ks][0], af[mi][ks][1], af[mi][ks][2], af[mi][ks][3],
                               bf[p][ks][2], bf[p][ks][3]);
                }
        if (more) {
            int nxt = cur ^ 1;
            *(uint2*)&Asb[nxt][arow * HSTR + akw] = f2h4(ra);
#pragma unroll
            for (int rr = 0; rr < 4; rr++)
                *(uint2*)&Bsb[nxt][(rr * 64 + arow) * HSTR + akw] = f2h4(rb[rr]);
        }
        __syncthreads();
        cur ^= 1;
    }

    // ---- epilogue phase 1: h = lrelu(acc+ai+aj)*mask + residual; row stats
    // red layout: rs [0,512), rq [512,1024), mean [1024,1088), inv [1088,1152)
#pragma unroll
    for (int mi = 0; mi < 2; mi++) {
#pragma unroll
        for (int half = 0; half < 2; half++) {
            int rloc = warp_m + mi * 16 + half * 8 + lg;    // 0..63
            int m = mbase + rloc;
            int b = m >> 14;
            int i = (m >> 7) & 127;
            int j = m & 127;
            float mv = mask[m];
            const float* aip = &ai[(size_t)((b << 7) + i) * 256];
            const float* ajp = &aj[(size_t)((b << 7) + j) * 256];
            const float* res = &A[(size_t)m * 256];
            float rs = 0.f, rq = 0.f;
#pragma unroll
            for (int ni = 0; ni < 4; ni++) {
                int col = warp_n + ni * 8 + 2 * lt;
                float2 a2 = *(const float2*)&aip[col];
                float2 j2 = *(const float2*)&ajp[col];
                float2 r2 = *(const float2*)&res[col];
                float v0 = c[mi][ni][2 * half + 0] + a2.x + j2.x;
                float v1 = c[mi][ni][2 * half + 1] + a2.y + j2.y;
                v0 = (v0 > 0.f ? v0 : ALPHA * v0) * mv + r2.x;
                v1 = (v1 > 0.f ? v1 : ALPHA * v1) * mv + r2.y;
                c[mi][ni][2 * half + 0] = v0;
                c[mi][ni][2 * half + 1] = v1;
                rs += v0 + v1;
                rq += v0 * v0 + v1 * v1;
            }
            rs += __shfl_xor_sync(0xffffffffu, rs, 1);
            rs += __shfl_xor_sync(0xffffffffu, rs, 2);
            rq += __shfl_xor_sync(0xffffffffu, rq, 1);
            rq += __shfl_xor_sync(0xffffffffu, rq, 2);
            if (lt == 0) {
                red[wn * 64 + rloc] = rs;
                red[512 + wn * 64 + rloc] = rq;
            }
        }
    }
    __syncthreads();
    if (tid < 64) {
        float S = 0.f, Q = 0.f;
#pragma unroll
        for (int w8 = 0; w8 < 8; w8++) {
            S += red[w8 * 64 + tid];
            Q += red[512 + w8 * 64 + tid];
        }
        float mean = S * (1.f / 256.f);
        float var = Q * (1.f / 256.f) - mean * mean;
        red[1024 + tid] = mean;
        red[1088 + tid] = rsqrtf(var + LN_EPS);
    }
    __syncthreads();

    // ---- epilogue phase 2: normalize, store, dot with v
#pragma unroll
    for (int mi = 0; mi < 2; mi++) {
#pragma unroll
        for (int half = 0; half < 2; half++) {
            int rloc = warp_m + mi * 16 + half * 8 + lg;
            int m = mbase + rloc;
            float mean = red[1024 + rloc];
            float inv = red[1088 + rloc];
            float dvp = 0.f;
#pragma unroll
            for (int ni = 0; ni < 4; ni++) {
                int col = warp_n + ni * 8 + 2 * lt;
                float2 g2 = *(const float2*)&lng[col];
                float2 b2 = *(const float2*)&lnb[col];
                float2 v2 = *(const float2*)&v[col];
                float y0 = (c[mi][ni][2 * half + 0] - mean) * inv * g2.x + b2.x;
                float y1 = (c[mi][ni][2 * half + 1] - mean) * inv * g2.y + b2.y;
                *(float2*)&out[(size_t)m * 256 + col] = make_float2(y0, y1);
                dvp += y0 * v2.x + y1 * v2.y;
            }
            dvp += __shfl_xor_sync(0xffffffffu, dvp, 1);
            dvp += __shfl_xor_sync(0xffffffffu, dvp, 2);
            if (lt == 0) red[wn * 64 + rloc] = dvp;   // stats at 1024+ untouched
        }
    }
    __syncthreads();
    if (tid < 64) {
        float S = 0.f;
#pragma unroll
        for (int w8 = 0; w8 < 8; w8++) S += red[w8 * 64 + tid];
        dotv[mbase + tid] = S;
    }
}

// ---------------- v = Wbp^T ub, w = Wfp^T ub, s = nodes·w (merged) ---------
__global__ void vws_kernel(const float* __restrict__ Wbp, const float* __restrict__ Wfp,
                           const float* __restrict__ ub, const float* __restrict__ nodes,
                           float* __restrict__ v, float* __restrict__ w,
                           float* __restrict__ s)
{
    __shared__ float ws[256];
    int k = threadIdx.x;
    float a = 0.f, b = 0.f;
    for (int c = 0; c < 256; c++) {
        float u = ub[c];
        a += u * Wbp[c * 256 + k];
        b += u * Wfp[c * 256 + k];
    }
    v[k] = a; w[k] = b;
    ws[k] = b;
    __syncthreads();
    float acc = 0.f;
    const float* rp = nodes + (size_t)k * 256;
    for (int c = 0; c < 256; c++) acc += rp[c] * ws[c];
    s[k] = acc;
}

// ---------------- attention + node update (LN fused) -----------------------
__global__ void __launch_bounds__(256)
attn_kernel(const float* __restrict__ dotv, const float* __restrict__ s,
            const float* __restrict__ nf, const float* __restrict__ mask,
            const float* __restrict__ nodes_old, const float* __restrict__ g,
            const float* __restrict__ bt, float* __restrict__ nodes_new)
{
    int bi = blockIdx.x;
    int b = bi >> 7, i = bi & 127;
    int t = threadIdx.x;
    __shared__ float sm_a[128];
    __shared__ float sred1[8], sred2[8];
    __shared__ float sm_m, sm_sum, sm_mean, sm_inv;

    if (t < 128) {
        int j = t;
        float mv = mask[b * 16384 + i * 128 + j];
        float r;
        if (mv > 0.f) {
            float dv = dotv[b * 16384 + j * 128 + i];
            r = dv + s[b * 128 + i] + s[b * 128 + j];
            r = r > 0.f ? r : ALPHA * r;
        } else {
            r = NEG_BIG;
        }
        sm_a[j] = r;
    }
    __syncthreads();
    if (t < 32) {
        float m = fmaxf(fmaxf(sm_a[t], sm_a[t + 32]), fmaxf(sm_a[t + 64], sm_a[t + 96]));
#pragma unroll
        for (int o = 16; o; o >>= 1) m = fmaxf(m, __shfl_xor_sync(0xffffffffu, m, o));
        if (t == 0) sm_m = m;
    }
    __syncthreads();
    if (t < 128) sm_a[t] = expf(sm_a[t] - sm_m);
    __syncthreads();
    if (t < 32) {
        float su = sm_a[t] + sm_a[t + 32] + sm_a[t + 64] + sm_a[t + 96];
#pragma unroll
        for (int o = 16; o; o >>= 1) su += __shfl_xor_sync(0xffffffffu, su, o);
        if (t == 0) sm_sum = su;
    }
    __syncthreads();
    float inv_sum = 1.f / sm_sum;

    int c = t;
    float acc = 0.f;
    const float* nfb = nf + (size_t)b * Nn * Cc + c;
#pragma unroll 4
    for (int j = 0; j < 128; j++) acc += sm_a[j] * nfb[(size_t)j * Cc];
    acc *= inv_sum;
    float h = (acc > 0.f ? acc : ALPHA * acc) + nodes_old[(size_t)(b * 128 + i) * 256 + c];

    int lane = t & 31, wp = t >> 5;
    float su = h, sq = h * h;
#pragma unroll
    for (int o = 16; o; o >>= 1) {
        su += __shfl_xor_sync(0xffffffffu, su, o);
        sq += __shfl_xor_sync(0xffffffffu, sq, o);
    }
    if (lane == 0) { sred1[wp] = su; sred2[wp] = sq; }
    __syncthreads();
    if (t == 0) {
        float S = 0.f, Q = 0.f;
#pragma unroll
        for (int w2 = 0; w2 < 8; w2++) { S += sred1[w2]; Q += sred2[w2]; }
        float mean = S * (1.f / 256.f);
        float var = Q * (1.f / 256.f) - mean * mean;
        sm_mean = mean;
        sm_inv = rsqrtf(var + LN_EPS);
    }
    __syncthreads();
    nodes_new[(size_t)(b * 128 + i) * 256 + c] = (h - sm_mean) * sm_inv * g[c] + bt[c];
}

// ---------------- edge logits: out[row,k] = e[row]·ecW[k] + ecb[k] ---------
__global__ void edge_logits_kernel(const float* __restrict__ e, const float* __restrict__ W,
                                   const float* __restrict__ bias, float* __restrict__ out)
{
    int warp = threadIdx.x >> 5, lane = threadIdx.x & 31;
    int row = blockIdx.x * 8 + warp;
    const float* rp = e + (size_t)row * 256;
    float x[8];
#pragma unroll
    for (int q = 0; q < 8; q++) x[q] = rp[lane + q * 32];
#pragma unroll
    for (int k = 0; k < KE_; k++) {
        float acc = 0.f;
#pragma unroll
        for (int q = 0; q < 8; q++) acc += x[q] * W[k * 256 + lane + q * 32];
#pragma unroll
        for (int o = 16; o; o >>= 1) acc += __shfl_xor_sync(0xffffffffu, acc, o);
        if (lane == 0) out[(size_t)row * KE_ + k] = acc + bias[k];
    }
}

// ---------------- host ------------------------------------------------------
extern "C" void kernel_launch(void* const* d_in, const int* in_sizes, int n_in,
                              void* d_out, int out_size)
{
    const float* nodes_in = (const float*)d_in[0];
    const float* edges_in = (const float*)d_in[1];
    const float* adj      = (const float*)d_in[2];
    const float* pnW = (const float*)d_in[3];
    const float* pnb = (const float*)d_in[4];
    const float* peW = (const float*)d_in[5];
    const float* peb = (const float*)d_in[6];
    const float* Wb  = (const float*)d_in[7];
    const float* Wbp = (const float*)d_in[8];
    const float* Wfp = (const float*)d_in[9];
    const float* ub  = (const float*)d_in[10];
    const float* Wf  = (const float*)d_in[11];
    const float* eln_g = (const float*)d_in[12];
    const float* eln_b = (const float*)d_in[13];
    const float* nln_g = (const float*)d_in[14];
    const float* nln_b = (const float*)d_in[15];
    const float* ncW = (const float*)d_in[16];
    const float* ncb = (const float*)d_in[17];
    const float* ecW = (const float*)d_in[18];
    const float* ecb = (const float*)d_in[19];

    float *eA, *eB, *n0, *n1, *ai_, *aj_, *nf_, *s_, *v_, *w_, *dv_;
    cudaGetSymbolAddress((void**)&eA, g_eA);
    cudaGetSymbolAddress((void**)&eB, g_eB);
    cudaGetSymbolAddress((void**)&n0, g_n0);
    cudaGetSymbolAddress((void**)&n1, g_n1);
    cudaGetSymbolAddress((void**)&ai_, g_ai);
    cudaGetSymbolAddress((void**)&aj_, g_aj);
    cudaGetSymbolAddress((void**)&nf_, g_nf);
    cudaGetSymbolAddress((void**)&s_, g_s);
    cudaGetSymbolAddress((void**)&v_, g_v);
    cudaGetSymbolAddress((void**)&w_, g_w);
    cudaGetSymbolAddress((void**)&dv_, g_dotv);

    cudaFuncSetAttribute(edge_fused, cudaFuncAttributeMaxDynamicSharedMemorySize,
                         EF_DSMEM);

    float* out = (float*)d_out;
    float* out_nodes = out;
    float* out_edges = out + NODES_SZ;

    // ping-pong schedule; layer 2 writes land directly in d_out (no copies)
    float* ebuf[4] = {eA, eB, eA, out_edges};
    float* nbuf[4] = {n0, n1, n0, out_nodes};

    dim3 bs(16, 16);

    // initial projections
    gemm_small<<<dim3(16, 16), bs>>>(nodes_in, pnW, pnb, nbuf[0], 256, 256, 128, 128);
    edge_proj_mma<<<dim3(2, 256), 512>>>(edges_in, peW, 64, 64, peb, ebuf[0]);

    for (int l = 0; l < 3; l++) {
        const float* Wb_l  = Wb  + (size_t)l * 256 * 768;
        const float* Wbp_l = Wbp + (size_t)l * 65536;
        const float* Wfp_l = Wfp + (size_t)l * 65536;
        const float* ub_l  = ub  + l * 256;
        const float* Wf_l  = Wf  + (size_t)l * 65536;
        float* ecur = ebuf[l]; float* enxt = ebuf[l + 1];
        float* ncur = nbuf[l]; float* nnxt = nbuf[l + 1];

        vws_kernel<<<1, 256>>>(Wbp_l, Wfp_l, ub_l, ncur, v_, w_, s_);
        node3_mma<<<dim3(4, 4, 3), 128>>>(ncur, Wb_l, Wf_l, ai_, aj_, nf_);

        edge_fused<<<512, 512, EF_DSMEM>>>(ecur, Wb_l + 256, ai_, aj_, adj,
                                           eln_g + l * 256, eln_b + l * 256, v_,
                                           enxt, dv_);
        attn_kernel<<<256, 256>>>(dv_, s_, nf_, adj, ncur,
                                  nln_g + l * 256, nln_b + l * 256, nnxt);
    }

    // final heads read directly from d_out regions
    gemm_small<<<dim3(7, 16), bs>>>(nbuf[3], ncW, ncb, out + NODES_SZ + EDGES_SZ,
                                    256, KN_, 256, 256);
    edge_logits_kernel<<<4096, 256>>>(ebuf[3], ecW, ecb,
                                      out + NODES_SZ + EDGES_SZ + 256 * KN_);
}